// round 1
// baseline (speedup 1.0000x reference)
#include <cuda_runtime.h>
#include <cuda_fp16.h>
#include <cstdint>

#define BB 4
#define SS 2048
#define EE 1024
#define HH 16
#define DD 64
#define MM (BB*SS)   // 8192 tokens

// ---------------- static scratch (no allocations allowed) ----------------
__device__ __half g_xh[MM*EE];          // x in fp16                      16 MB
__device__ __half g_wt[4][EE*EE];       // Wq,Wk,Wv,Wo transposed [n][k]   8 MB
__device__ __half g_q [BB*HH*SS*DD];    // Q rope'd  [b,h,s,d]            16 MB
__device__ __half g_k [BB*HH*SS*DD];    // K rope'd  [b,h,s,d]            16 MB
__device__ __half g_vt[BB*HH*DD*SS];    // V transposed [b,h,d,s]         16 MB
__device__ __half g_oc[MM*EE];          // attention output [tok, h*64+d] 16 MB

__device__ __forceinline__ void mma16816(float c[4], const uint32_t a[4],
                                         uint32_t b0, uint32_t b1) {
    asm volatile(
        "mma.sync.aligned.m16n8k16.row.col.f32.f16.f16.f32 "
        "{%0,%1,%2,%3}, {%4,%5,%6,%7}, {%8,%9}, {%0,%1,%2,%3};\n"
        : "+f"(c[0]), "+f"(c[1]), "+f"(c[2]), "+f"(c[3])
        : "r"(a[0]), "r"(a[1]), "r"(a[2]), "r"(a[3]), "r"(b0), "r"(b1));
}

// ---------------- conversions ----------------
__global__ void cvt_x_kernel(const float* __restrict__ x) {
    int i = (blockIdx.x * blockDim.x + threadIdx.x) * 4;
    float4 v = *(const float4*)(x + i);
    __half2* o = (__half2*)(g_xh + i);
    o[0] = __floats2half2_rn(v.x, v.y);
    o[1] = __floats2half2_rn(v.z, v.w);
}

// W [k][n] fp32  ->  g_wt[which] [n][k] fp16 (tiled transpose)
__global__ void cvt_w_kernel(const float* __restrict__ W, int which) {
    __shared__ float t[32][33];
    int bx = blockIdx.x * 32, by = blockIdx.y * 32;
#pragma unroll
    for (int i = 0; i < 32; i += 8)
        t[threadIdx.y + i][threadIdx.x] = W[(by + threadIdx.y + i) * EE + bx + threadIdx.x];
    __syncthreads();
#pragma unroll
    for (int i = 0; i < 32; i += 8)
        g_wt[which][(bx + threadIdx.y + i) * EE + (by + threadIdx.x)] =
            __float2half(t[threadIdx.x][threadIdx.y + i]);
}

// ---------------- GEMM: C[m,n] = sum_k A[m,k]*Bt[n,k] + bias ----------------
// mode 0: Q proj + RoPE -> g_q[b,h,s,d]
// mode 1: K proj + RoPE -> g_k[b,h,s,d]
// mode 2: V proj        -> g_vt[b,h,d,s]
// mode 3: final  A=g_oc -> fp32 out + bias
__global__ __launch_bounds__(128) void gemm_kernel(int mode,
                                                   const float* __restrict__ bias,
                                                   float* __restrict__ out32) {
    const __half* A  = (mode == 3) ? g_oc : g_xh;
    const __half* Bt = g_wt[mode];

    __shared__ __align__(16) __half As[64][24];
    __shared__ __align__(16) __half Bs[64][24];

    int tid = threadIdx.x, w = tid >> 5, l = tid & 31, g = l >> 2, tq = l & 3;
    int bm = blockIdx.y * 64, bn = blockIdx.x * 64;

    float acc[8][4];
#pragma unroll
    for (int j = 0; j < 8; j++)
#pragma unroll
        for (int i = 0; i < 4; i++) acc[j][i] = 0.f;

    int arow = tid >> 1, ac8 = (tid & 1) * 8;
    const __half* Ap = A  + (bm + arow) * EE + ac8;
    const __half* Bp = Bt + (bn + arow) * EE + ac8;

    for (int k0 = 0; k0 < EE; k0 += 16) {
        uint4 av = *(const uint4*)(Ap + k0);
        uint4 bv = *(const uint4*)(Bp + k0);
        *(uint4*)&As[arow][ac8] = av;
        *(uint4*)&Bs[arow][ac8] = bv;
        __syncthreads();
        uint32_t a[4];
        a[0] = *(const uint32_t*)&As[w * 16 + g    ][tq * 2];
        a[1] = *(const uint32_t*)&As[w * 16 + g + 8][tq * 2];
        a[2] = *(const uint32_t*)&As[w * 16 + g    ][tq * 2 + 8];
        a[3] = *(const uint32_t*)&As[w * 16 + g + 8][tq * 2 + 8];
#pragma unroll
        for (int j = 0; j < 8; j++) {
            uint32_t b0 = *(const uint32_t*)&Bs[j * 8 + g][tq * 2];
            uint32_t b1 = *(const uint32_t*)&Bs[j * 8 + g][tq * 2 + 8];
            mma16816(acc[j], a, b0, b1);
        }
        __syncthreads();
    }

    // -------- epilogue --------
    int r0 = bm + w * 16 + g;        // token row (and r0+8)
    int b_ = r0 >> 11;               // batch (S=2048)
    int s0 = r0 & 2047;              // seq position
    int h  = blockIdx.x;             // head (BN==64==D, N tile == head)

    if (mode == 3) {
#pragma unroll
        for (int j = 0; j < 8; j++) {
            int n = bn + j * 8 + tq * 2;
            float bv0 = bias[n], bv1 = bias[n + 1];
            float2 v0 = make_float2(acc[j][0] + bv0, acc[j][1] + bv1);
            float2 v1 = make_float2(acc[j][2] + bv0, acc[j][3] + bv1);
            *(float2*)(out32 + (long)r0 * EE + n)       = v0;
            *(float2*)(out32 + (long)(r0 + 8) * EE + n) = v1;
        }
        return;
    }

#pragma unroll
    for (int j = 0; j < 8; j++) {
        int n = bn + j * 8 + tq * 2;
        float bv0 = bias[n], bv1 = bias[n + 1];
        acc[j][0] += bv0; acc[j][1] += bv1;
        acc[j][2] += bv0; acc[j][3] += bv1;
    }

    if (mode == 2) {  // V -> transposed [b,h,d,s]
        long base = (long)(b_ * HH + h) * DD;
#pragma unroll
        for (int j = 0; j < 8; j++) {
            int d = j * 8 + tq * 2;
            g_vt[(base + d    ) * SS + s0    ] = __float2half(acc[j][0]);
            g_vt[(base + d + 1) * SS + s0    ] = __float2half(acc[j][1]);
            g_vt[(base + d    ) * SS + s0 + 8] = __float2half(acc[j][2]);
            g_vt[(base + d + 1) * SS + s0 + 8] = __float2half(acc[j][3]);
        }
        return;
    }

    // RoPE (modes 0/1). Thread holds cols d and d+32 in tiles jp and jp+4.
    __half* out = (mode == 0) ? g_q : g_k;
    long rowbase = (long)(b_ * HH + h) * SS;
    const float LOG2_BASE = 13.28771237954945f;  // log2(10000)
#pragma unroll
    for (int jp = 0; jp < 4; jp++) {
        int d = jp * 8 + tq * 2;  // 0..30 even
        float invf0 = exp2f(-(float)d       * (LOG2_BASE / 32.f));
        float invf1 = exp2f(-(float)(d + 1) * (LOG2_BASE / 32.f));
#pragma unroll
        for (int rr = 0; rr < 2; rr++) {
            int s = s0 + rr * 8;
            float sn0, cs0, sn1, cs1;
            sincosf((float)s * invf0, &sn0, &cs0);
            sincosf((float)s * invf1, &sn1, &cs1);
            float x1a = acc[jp][rr * 2 + 0],     x1b = acc[jp][rr * 2 + 1];
            float x2a = acc[jp + 4][rr * 2 + 0], x2b = acc[jp + 4][rr * 2 + 1];
            __half2 lo = __floats2half2_rn(x1a * cs0 - x2a * sn0, x1b * cs1 - x2b * sn1);
            __half2 hi = __floats2half2_rn(x2a * cs0 + x1a * sn0, x2b * cs1 + x1b * sn1);
            *(__half2*)(out + (rowbase + s) * DD + d)      = lo;
            *(__half2*)(out + (rowbase + s) * DD + d + 32) = hi;
        }
    }
}

// ---------------- flash attention (BM=BN=64, 4 warps) ----------------
__global__ __launch_bounds__(128) void flash_kernel(const unsigned char* __restrict__ mask) {
    int bh = blockIdx.y;          // b*H + h
    int b_ = bh >> 4;
    int h  = bh & 15;
    int qt = blockIdx.x;          // q tile

    __shared__ __align__(16) __half Qs[64][72];
    __shared__ __align__(16) __half Ks[64][72];
    __shared__ __align__(16) __half Vs[64][72];
    __shared__ float msks[64];

    int tid = threadIdx.x, w = tid >> 5, l = tid & 31, g = l >> 2, tq = l & 3;

    const __half* Qg = g_q + ((long)bh * SS + qt * 64) * DD;
#pragma unroll
    for (int it = 0; it < 4; it++) {
        int u = tid + 128 * it, row = u >> 3, c8 = (u & 7) * 8;
        *(uint4*)&Qs[row][c8] = *(const uint4*)(Qg + row * 64 + c8);
    }

    float accO[8][4];
#pragma unroll
    for (int j = 0; j < 8; j++)
#pragma unroll
        for (int i = 0; i < 4; i++) accO[j][i] = 0.f;
    float mi0 = -1e30f, mi1 = -1e30f, li0 = 0.f, li1 = 0.f;

    for (int t = 0; t < SS / 64; t++) {
        const __half* Kg = g_k  + ((long)bh * SS + t * 64) * DD;
        const __half* Vg = g_vt + ((long)bh * DD) * SS + t * 64;
        __syncthreads();  // previous iter done reading Ks/Vs
#pragma unroll
        for (int it = 0; it < 4; it++) {
            int u = tid + 128 * it, row = u >> 3, c8 = (u & 7) * 8;
            *(uint4*)&Ks[row][c8] = *(const uint4*)(Kg + row * 64 + c8);
            *(uint4*)&Vs[row][c8] = *(const uint4*)(Vg + (long)row * SS + c8);
        }
        if (tid < 64)
            msks[tid] = mask[b_ * SS + t * 64 + tid] ? -1e30f : 0.f;
        __syncthreads();

        // S = Q @ K^T  (scaled)
        float sc[8][4];
#pragma unroll
        for (int j = 0; j < 8; j++)
#pragma unroll
            for (int i = 0; i < 4; i++) sc[j][i] = 0.f;
#pragma unroll
        for (int kk = 0; kk < 4; kk++) {
            uint32_t a[4];
            a[0] = *(const uint32_t*)&Qs[w * 16 + g    ][kk * 16 + tq * 2];
            a[1] = *(const uint32_t*)&Qs[w * 16 + g + 8][kk * 16 + tq * 2];
            a[2] = *(const uint32_t*)&Qs[w * 16 + g    ][kk * 16 + tq * 2 + 8];
            a[3] = *(const uint32_t*)&Qs[w * 16 + g + 8][kk * 16 + tq * 2 + 8];
#pragma unroll
            for (int j = 0; j < 8; j++) {
                uint32_t b0 = *(const uint32_t*)&Ks[j * 8 + g][kk * 16 + tq * 2];
                uint32_t b1 = *(const uint32_t*)&Ks[j * 8 + g][kk * 16 + tq * 2 + 8];
                mma16816(sc[j], a, b0, b1);
            }
        }
#pragma unroll
        for (int j = 0; j < 8; j++) {
            float m0 = msks[j * 8 + tq * 2], m1 = msks[j * 8 + tq * 2 + 1];
            sc[j][0] = sc[j][0] * 0.125f + m0;
            sc[j][1] = sc[j][1] * 0.125f + m1;
            sc[j][2] = sc[j][2] * 0.125f + m0;
            sc[j][3] = sc[j][3] * 0.125f + m1;
        }
        // row maxes (rows r0 = top, r1 = bottom of the 16-row warp chunk)
        float mx0 = -1e30f, mx1 = -1e30f;
#pragma unroll
        for (int j = 0; j < 8; j++) {
            mx0 = fmaxf(mx0, fmaxf(sc[j][0], sc[j][1]));
            mx1 = fmaxf(mx1, fmaxf(sc[j][2], sc[j][3]));
        }
        mx0 = fmaxf(mx0, __shfl_xor_sync(0xffffffff, mx0, 1));
        mx0 = fmaxf(mx0, __shfl_xor_sync(0xffffffff, mx0, 2));
        mx1 = fmaxf(mx1, __shfl_xor_sync(0xffffffff, mx1, 1));
        mx1 = fmaxf(mx1, __shfl_xor_sync(0xffffffff, mx1, 2));
        float mn0 = fmaxf(mi0, mx0), mn1 = fmaxf(mi1, mx1);
        float rs0f = __expf(mi0 - mn0), rs1f = __expf(mi1 - mn1);
        mi0 = mn0; mi1 = mn1;

        // P = exp(S - m), packed directly into A fragments
        uint32_t pa[4][4];
        float sum0 = 0.f, sum1 = 0.f;
#pragma unroll
        for (int j = 0; j < 8; j++) {
            float p0 = __expf(sc[j][0] - mn0), p1 = __expf(sc[j][1] - mn0);
            float p2 = __expf(sc[j][2] - mn1), p3 = __expf(sc[j][3] - mn1);
            sum0 += p0 + p1; sum1 += p2 + p3;
            __half2 h01 = __floats2half2_rn(p0, p1);
            __half2 h23 = __floats2half2_rn(p2, p3);
            int kk = j >> 1;
            if ((j & 1) == 0) {
                pa[kk][0] = *(uint32_t*)&h01; pa[kk][1] = *(uint32_t*)&h23;
            } else {
                pa[kk][2] = *(uint32_t*)&h01; pa[kk][3] = *(uint32_t*)&h23;
            }
        }
        sum0 += __shfl_xor_sync(0xffffffff, sum0, 1);
        sum0 += __shfl_xor_sync(0xffffffff, sum0, 2);
        sum1 += __shfl_xor_sync(0xffffffff, sum1, 1);
        sum1 += __shfl_xor_sync(0xffffffff, sum1, 2);
        li0 = li0 * rs0f + sum0;
        li1 = li1 * rs1f + sum1;
#pragma unroll
        for (int j = 0; j < 8; j++) {
            accO[j][0] *= rs0f; accO[j][1] *= rs0f;
            accO[j][2] *= rs1f; accO[j][3] *= rs1f;
        }
        // O += P @ V   (Vs is [d][kv], so col-major B is a contiguous half2)
#pragma unroll
        for (int kk = 0; kk < 4; kk++) {
#pragma unroll
            for (int j = 0; j < 8; j++) {
                uint32_t b0 = *(const uint32_t*)&Vs[j * 8 + g][kk * 16 + tq * 2];
                uint32_t b1 = *(const uint32_t*)&Vs[j * 8 + g][kk * 16 + tq * 2 + 8];
                mma16816(accO[j], pa[kk], b0, b1);
            }
        }
    }

    float inv0 = 1.f / li0, inv1 = 1.f / li1;
    int q0 = qt * 64 + w * 16 + g;
    long row0 = (long)(b_ * SS + q0) * EE + h * 64;
    long row1 = (long)(b_ * SS + q0 + 8) * EE + h * 64;
#pragma unroll
    for (int j = 0; j < 8; j++) {
        int d0 = j * 8 + tq * 2;
        __half2 o0 = __floats2half2_rn(accO[j][0] * inv0, accO[j][1] * inv0);
        __half2 o1 = __floats2half2_rn(accO[j][2] * inv1, accO[j][3] * inv1);
        *(__half2*)(g_oc + row0 + d0) = o0;
        *(__half2*)(g_oc + row1 + d0) = o1;
    }
}

// ---------------- launch ----------------
extern "C" void kernel_launch(void* const* d_in, const int* in_sizes, int n_in,
                              void* d_out, int out_size) {
    const float* x  = (const float*)d_in[0];
    const float* Wq = (const float*)d_in[1];
    const float* bq = (const float*)d_in[2];
    const float* Wk = (const float*)d_in[3];
    const float* bk = (const float*)d_in[4];
    const float* Wv = (const float*)d_in[5];
    const float* bv = (const float*)d_in[6];
    const float* Wo = (const float*)d_in[7];
    const float* bo = (const float*)d_in[8];
    const unsigned char* mask = (const unsigned char*)d_in[9];
    float* out = (float*)d_out;

    cvt_x_kernel<<<MM * EE / 1024, 256>>>(x);

    dim3 tw(32, 8), gw(EE / 32, EE / 32);
    cvt_w_kernel<<<gw, tw>>>(Wq, 0);
    cvt_w_kernel<<<gw, tw>>>(Wk, 1);
    cvt_w_kernel<<<gw, tw>>>(Wv, 2);
    cvt_w_kernel<<<gw, tw>>>(Wo, 3);

    dim3 gg(EE / 64, MM / 64);
    gemm_kernel<<<gg, 128>>>(0, bq, nullptr);
    gemm_kernel<<<gg, 128>>>(1, bk, nullptr);
    gemm_kernel<<<gg, 128>>>(2, bv, nullptr);

    flash_kernel<<<dim3(SS / 64, BB * HH), 128>>>(mask);

    gemm_kernel<<<gg, 128>>>(3, bo, out);
}

// round 2
// speedup vs baseline: 1.0652x; 1.0652x over previous
#include <cuda_runtime.h>
#include <cuda_fp16.h>
#include <cstdint>

#define BB 4
#define SS 2048
#define EE 1024
#define HH 16
#define DD 64
#define MM (BB*SS)   // 8192 tokens

// ---------------- static scratch ----------------
__device__ __align__(256) __half g_xh[MM*EE];
__device__ __align__(256) __half g_wt[4][EE*EE];      // transposed [n][k]
__device__ __align__(256) __half g_q [BB*HH*SS*DD];   // [b,h,s,d]
__device__ __align__(256) __half g_k [BB*HH*SS*DD];   // [b,h,s,d]
__device__ __align__(256) __half g_vt[BB*HH*DD*SS];   // [b,h,d,s]
__device__ __align__(256) __half g_oc[MM*EE];         // [tok, h*64+d]
__device__ float g_maskf[BB*SS];

__device__ __forceinline__ void mma16816(float c[4], const uint32_t a[4],
                                         uint32_t b0, uint32_t b1) {
    asm volatile(
        "mma.sync.aligned.m16n8k16.row.col.f32.f16.f16.f32 "
        "{%0,%1,%2,%3}, {%4,%5,%6,%7}, {%8,%9}, {%0,%1,%2,%3};\n"
        : "+f"(c[0]), "+f"(c[1]), "+f"(c[2]), "+f"(c[3])
        : "r"(a[0]), "r"(a[1]), "r"(a[2]), "r"(a[3]), "r"(b0), "r"(b1));
}
__device__ __forceinline__ void ldsm4(uint32_t &r0, uint32_t &r1,
                                      uint32_t &r2, uint32_t &r3, uint32_t a) {
    asm volatile("ldmatrix.sync.aligned.m8n8.x4.shared.b16 {%0,%1,%2,%3}, [%4];\n"
                 : "=r"(r0), "=r"(r1), "=r"(r2), "=r"(r3) : "r"(a));
}
__device__ __forceinline__ void cp16(void* dst, const void* src) {
    uint32_t d = (uint32_t)__cvta_generic_to_shared(dst);
    asm volatile("cp.async.cg.shared.global [%0], [%1], 16;\n" :: "r"(d), "l"(src));
}
__device__ __forceinline__ void cp_commit() { asm volatile("cp.async.commit_group;\n"); }
template<int N> __device__ __forceinline__ void cp_wait() {
    asm volatile("cp.async.wait_group %0;\n" :: "n"(N));
}

// ---------------- conversions ----------------
__global__ void cvt_x_kernel(const float* __restrict__ x) {
    int i = (blockIdx.x * blockDim.x + threadIdx.x) * 4;
    float4 v = *(const float4*)(x + i);
    __half2* o = (__half2*)(g_xh + i);
    o[0] = __floats2half2_rn(v.x, v.y);
    o[1] = __floats2half2_rn(v.z, v.w);
}
__global__ void cvt_mask_kernel(const unsigned char* __restrict__ m) {
    int i = blockIdx.x * blockDim.x + threadIdx.x;
    g_maskf[i] = m[i] ? -1e30f : 0.f;
}
__global__ void cvt_w_kernel(const float* __restrict__ W, int which) {
    __shared__ float t[32][33];
    int bx = blockIdx.x * 32, by = blockIdx.y * 32;
#pragma unroll
    for (int i = 0; i < 32; i += 8)
        t[threadIdx.y + i][threadIdx.x] = W[(by + threadIdx.y + i) * EE + bx + threadIdx.x];
    __syncthreads();
#pragma unroll
    for (int i = 0; i < 32; i += 8)
        g_wt[which][(bx + threadIdx.y + i) * EE + (by + threadIdx.x)] =
            __float2half(t[threadIdx.x][threadIdx.y + i]);
}

// ---------------- GEMM: BM=128 BN=64 BK=32, 256 thr, cp.async double buffer ----
// mode 0: Q proj + RoPE -> g_q   mode 1: K proj + RoPE -> g_k
// mode 2: V proj -> g_vt (transposed)   mode 3: O proj -> fp32 out
__global__ __launch_bounds__(256) void gemm_kernel(int mode,
                                                   const float* __restrict__ bias,
                                                   float* __restrict__ out32) {
    const __half* A  = (mode == 3) ? g_oc : g_xh;
    const __half* Bt = g_wt[mode];

    __shared__ __align__(16) __half As[2][128][40];  // pad 8 halves, 80B rows
    __shared__ __align__(16) __half Bs[2][64][40];

    int tid = threadIdx.x, w = tid >> 5, l = tid & 31, g = l >> 2, tq = l & 3;
    int bm = blockIdx.y * 128, bn = blockIdx.x * 64;

    float acc[8][4];
#pragma unroll
    for (int j = 0; j < 8; j++)
#pragma unroll
        for (int i = 0; i < 4; i++) acc[j][i] = 0.f;

    const __half* Ap = A  + (long)bm * EE;
    const __half* Bp = Bt + (long)bn * EE;
    int lr = tid >> 2, lc = (tid & 3) * 8;

    uint32_t AsB = (uint32_t)__cvta_generic_to_shared(&As[0][0][0]);
    uint32_t BsB = (uint32_t)__cvta_generic_to_shared(&Bs[0][0][0]);
    int bi = l >> 3, rin = l & 7;
    // A-frag ldmatrix offset (bytes): row = w*16 + 8*(bi&1) + rin, col = 8*(bi>>1)
    uint32_t aoff = (uint32_t)(((w * 16 + ((bi & 1) << 3) + rin) * 40 + ((bi >> 1) << 3)) * 2);
    // B-frag: row-in-pairblock = 8*(bi>>1) + rin, col = 8*(bi&1)
    uint32_t boff = (uint32_t)(((((bi >> 1) << 3) + rin) * 40 + ((bi & 1) << 3)) * 2);

#define GEMM_LOAD(s, k0)                                                          \
    do {                                                                          \
        cp16(&As[s][lr][lc],      Ap + (long)lr * EE + (k0) + lc);                \
        cp16(&As[s][lr + 64][lc], Ap + (long)(lr + 64) * EE + (k0) + lc);         \
        cp16(&Bs[s][lr][lc],      Bp + (long)lr * EE + (k0) + lc);                \
    } while (0)

    GEMM_LOAD(0, 0);
    cp_commit();

    for (int i = 0; i < 32; i++) {
        cp_wait<0>();
        __syncthreads();
        if (i < 31) { GEMM_LOAD((i + 1) & 1, (i + 1) * 32); cp_commit(); }
        int s = i & 1;
        uint32_t abase = AsB + s * 10240 + aoff;
        uint32_t bbase = BsB + s * 5120 + boff;
        uint32_t a[2][4];
#pragma unroll
        for (int kk = 0; kk < 2; kk++)
            ldsm4(a[kk][0], a[kk][1], a[kk][2], a[kk][3], abase + kk * 32);
#pragma unroll
        for (int jp = 0; jp < 4; jp++) {
#pragma unroll
            for (int kk = 0; kk < 2; kk++) {
                uint32_t b0, b1, b2, b3;
                ldsm4(b0, b1, b2, b3, bbase + jp * (16 * 80) + kk * 32);
                mma16816(acc[2 * jp],     a[kk], b0, b1);
                mma16816(acc[2 * jp + 1], a[kk], b2, b3);
            }
        }
    }

    // -------- epilogue --------
    int r0 = bm + w * 16 + g;
    int b_ = r0 >> 11;
    int s0 = r0 & 2047;
    int h  = blockIdx.x;

    if (mode == 3) {
#pragma unroll
        for (int j = 0; j < 8; j++) {
            int n = bn + j * 8 + tq * 2;
            float bv0 = bias[n], bv1 = bias[n + 1];
            float2 v0 = make_float2(acc[j][0] + bv0, acc[j][1] + bv1);
            float2 v1 = make_float2(acc[j][2] + bv0, acc[j][3] + bv1);
            *(float2*)(out32 + (long)r0 * EE + n)       = v0;
            *(float2*)(out32 + (long)(r0 + 8) * EE + n) = v1;
        }
        return;
    }

#pragma unroll
    for (int j = 0; j < 8; j++) {
        int n = bn + j * 8 + tq * 2;
        float bv0 = bias[n], bv1 = bias[n + 1];
        acc[j][0] += bv0; acc[j][1] += bv1;
        acc[j][2] += bv0; acc[j][3] += bv1;
    }

    if (mode == 2) {  // V -> [b,h,d,s]
        long base = (long)(b_ * HH + h) * DD;
#pragma unroll
        for (int j = 0; j < 8; j++) {
            int d = j * 8 + tq * 2;
            g_vt[(base + d    ) * SS + s0    ] = __float2half(acc[j][0]);
            g_vt[(base + d + 1) * SS + s0    ] = __float2half(acc[j][1]);
            g_vt[(base + d    ) * SS + s0 + 8] = __float2half(acc[j][2]);
            g_vt[(base + d + 1) * SS + s0 + 8] = __float2half(acc[j][3]);
        }
        return;
    }

    // RoPE (modes 0/1)
    __half* out = (mode == 0) ? g_q : g_k;
    long rowbase = (long)(b_ * HH + h) * SS;
    const float LOG2_BASE = 13.28771237954945f;
#pragma unroll
    for (int jp = 0; jp < 4; jp++) {
        int d = jp * 8 + tq * 2;
        float invf0 = exp2f(-(float)d       * (LOG2_BASE / 32.f));
        float invf1 = exp2f(-(float)(d + 1) * (LOG2_BASE / 32.f));
#pragma unroll
        for (int rr = 0; rr < 2; rr++) {
            int s = s0 + rr * 8;
            float sn0, cs0, sn1, cs1;
            sincosf((float)s * invf0, &sn0, &cs0);
            sincosf((float)s * invf1, &sn1, &cs1);
            float x1a = acc[jp][rr * 2 + 0],     x1b = acc[jp][rr * 2 + 1];
            float x2a = acc[jp + 4][rr * 2 + 0], x2b = acc[jp + 4][rr * 2 + 1];
            __half2 lo = __floats2half2_rn(x1a * cs0 - x2a * sn0, x1b * cs1 - x2b * sn1);
            __half2 hi = __floats2half2_rn(x2a * cs0 + x1a * sn0, x2b * cs1 + x1b * sn1);
            *(__half2*)(out + (rowbase + s) * DD + d)      = lo;
            *(__half2*)(out + (rowbase + s) * DD + d + 32) = hi;
        }
    }
}

// ---------------- flash attention: BM=128 q rows, KV tile 64, 8 warps --------
__global__ __launch_bounds__(256) void flash_kernel() {
    int bh = blockIdx.y;
    int b_ = bh >> 4;
    int h  = bh & 15;
    int qt = blockIdx.x;

    // XOR-swizzled 128B rows, no padding: 16KB + 16KB + 16KB = 48KB
    __shared__ __align__(16) __half Qs[128][64];
    __shared__ __align__(16) __half Ks[2][64][64];
    __shared__ __align__(16) __half Vs[2][64][64];

    int tid = threadIdx.x, w = tid >> 5, l = tid & 31, g = l >> 2, tq = l & 3;

    const __half* Qg = g_q  + ((long)bh * SS + qt * 128) * DD;
    const __half* Kg0 = g_k  + (long)bh * SS * DD;
    const __half* Vg0 = g_vt + (long)bh * DD * SS;

    // Q: 128 rows x 8 chunks
#pragma unroll
    for (int it = 0; it < 4; it++) {
        int c = tid + 256 * it, r = c >> 3, cc = c & 7;
        cp16(&Qs[r][((cc ^ (r & 7)) << 3)], Qg + r * 64 + cc * 8);
    }
    cp_commit();

#define KV_LOAD(s, t)                                                             \
    do {                                                                          \
        const __half* Kg = Kg0 + (long)(t) * 64 * DD;                             \
        const __half* Vg = Vg0 + (t) * 64;                                        \
        _Pragma("unroll")                                                         \
        for (int it = 0; it < 2; it++) {                                          \
            int c = tid + 256 * it, r = c >> 3, cc = c & 7;                       \
            cp16(&Ks[s][r][((cc ^ (r & 7)) << 3)], Kg + r * 64 + cc * 8);         \
            cp16(&Vs[s][r][((cc ^ (r & 7)) << 3)], Vg + (long)r * SS + cc * 8);   \
        }                                                                         \
    } while (0)

    KV_LOAD(0, 0);
    cp_commit();

    uint32_t QsB = (uint32_t)__cvta_generic_to_shared(&Qs[0][0]);
    uint32_t KsB = (uint32_t)__cvta_generic_to_shared(&Ks[0][0][0]);
    uint32_t VsB = (uint32_t)__cvta_generic_to_shared(&Vs[0][0][0]);
    int bi = l >> 3, rin = l & 7;

    cp_wait<1>();   // Q group done
    __syncthreads();

    // Q fragments -> registers (row = w*16 + 8*(bi&1) + rin; col = 8*(bi>>1) + kk*16)
    uint32_t qf[4][4];
    {
        uint32_t qrowb = QsB + (uint32_t)((w * 16 + ((bi & 1) << 3) + rin) * 128);
        int qcb = bi >> 1;
#pragma unroll
        for (int kk = 0; kk < 4; kk++)
            ldsm4(qf[kk][0], qf[kk][1], qf[kk][2], qf[kk][3],
                  qrowb + (uint32_t)((((kk * 2 + qcb) ^ rin) << 4)));
    }

    // K/V frag base: row-in-pairblock = 8*(bi>>1) + rin; col chunk = kk*2 + (bi&1)
    uint32_t kvro = (uint32_t)(((((bi >> 1) << 3) + rin)) * 128);
    int kcb = bi & 1;

    float accO[8][4];
#pragma unroll
    for (int j = 0; j < 8; j++)
#pragma unroll
        for (int i = 0; i < 4; i++) accO[j][i] = 0.f;
    float mi0 = -1e30f, mi1 = -1e30f, li0 = 0.f, li1 = 0.f;

    const float* mrow = g_maskf + b_ * SS;

    for (int t = 0; t < SS / 64; t++) {
        cp_wait<0>();
        __syncthreads();
        if (t < SS / 64 - 1) { KV_LOAD((t + 1) & 1, t + 1); cp_commit(); }
        int s = t & 1;
        uint32_t kbase = KsB + s * 8192 + kvro;
        uint32_t vbase = VsB + s * 8192 + kvro;

        // S = Q @ K^T
        float sc[8][4];
#pragma unroll
        for (int j = 0; j < 8; j++)
#pragma unroll
            for (int i = 0; i < 4; i++) sc[j][i] = 0.f;
#pragma unroll
        for (int kk = 0; kk < 4; kk++) {
#pragma unroll
            for (int jp = 0; jp < 4; jp++) {
                uint32_t b0, b1, b2, b3;
                ldsm4(b0, b1, b2, b3, kbase + jp * 2048 + ((((kk * 2 + kcb) ^ rin)) << 4));
                mma16816(sc[2 * jp],     qf[kk], b0, b1);
                mma16816(sc[2 * jp + 1], qf[kk], b2, b3);
            }
        }
        // scale + mask
#pragma unroll
        for (int j = 0; j < 8; j++) {
            float2 mv = *(const float2*)(mrow + t * 64 + j * 8 + tq * 2);
            sc[j][0] = sc[j][0] * 0.125f + mv.x;
            sc[j][1] = sc[j][1] * 0.125f + mv.y;
            sc[j][2] = sc[j][2] * 0.125f + mv.x;
            sc[j][3] = sc[j][3] * 0.125f + mv.y;
        }
        // online softmax
        float mx0 = -1e30f, mx1 = -1e30f;
#pragma unroll
        for (int j = 0; j < 8; j++) {
            mx0 = fmaxf(mx0, fmaxf(sc[j][0], sc[j][1]));
            mx1 = fmaxf(mx1, fmaxf(sc[j][2], sc[j][3]));
        }
        mx0 = fmaxf(mx0, __shfl_xor_sync(0xffffffff, mx0, 1));
        mx0 = fmaxf(mx0, __shfl_xor_sync(0xffffffff, mx0, 2));
        mx1 = fmaxf(mx1, __shfl_xor_sync(0xffffffff, mx1, 1));
        mx1 = fmaxf(mx1, __shfl_xor_sync(0xffffffff, mx1, 2));
        float mn0 = fmaxf(mi0, mx0), mn1 = fmaxf(mi1, mx1);
        float rs0f = __expf(mi0 - mn0), rs1f = __expf(mi1 - mn1);
        mi0 = mn0; mi1 = mn1;

        uint32_t pa[4][4];
        float sum0 = 0.f, sum1 = 0.f;
#pragma unroll
        for (int j = 0; j < 8; j++) {
            float p0 = __expf(sc[j][0] - mn0), p1 = __expf(sc[j][1] - mn0);
            float p2 = __expf(sc[j][2] - mn1), p3 = __expf(sc[j][3] - mn1);
            sum0 += p0 + p1; sum1 += p2 + p3;
            __half2 h01 = __floats2half2_rn(p0, p1);
            __half2 h23 = __floats2half2_rn(p2, p3);
            int kk = j >> 1;
            if ((j & 1) == 0) { pa[kk][0] = *(uint32_t*)&h01; pa[kk][1] = *(uint32_t*)&h23; }
            else             { pa[kk][2] = *(uint32_t*)&h01; pa[kk][3] = *(uint32_t*)&h23; }
        }
        sum0 += __shfl_xor_sync(0xffffffff, sum0, 1);
        sum0 += __shfl_xor_sync(0xffffffff, sum0, 2);
        sum1 += __shfl_xor_sync(0xffffffff, sum1, 1);
        sum1 += __shfl_xor_sync(0xffffffff, sum1, 2);
        li0 = li0 * rs0f + sum0;
        li1 = li1 * rs1f + sum1;
#pragma unroll
        for (int j = 0; j < 8; j++) {
            accO[j][0] *= rs0f; accO[j][1] *= rs0f;
            accO[j][2] *= rs1f; accO[j][3] *= rs1f;
        }
        // O += P @ V
#pragma unroll
        for (int kk = 0; kk < 4; kk++) {
#pragma unroll
            for (int jp = 0; jp < 4; jp++) {
                uint32_t b0, b1, b2, b3;
                ldsm4(b0, b1, b2, b3, vbase + jp * 2048 + ((((kk * 2 + kcb) ^ rin)) << 4));
                mma16816(accO[2 * jp],     pa[kk], b0, b1);
                mma16816(accO[2 * jp + 1], pa[kk], b2, b3);
            }
        }
    }

    float inv0 = 1.f / li0, inv1 = 1.f / li1;
    int q0 = qt * 128 + w * 16 + g;
    long row0 = (long)(b_ * SS + q0) * EE + h * 64;
    long row1 = (long)(b_ * SS + q0 + 8) * EE + h * 64;
#pragma unroll
    for (int j = 0; j < 8; j++) {
        int d0 = j * 8 + tq * 2;
        __half2 o0 = __floats2half2_rn(accO[j][0] * inv0, accO[j][1] * inv0);
        __half2 o1 = __floats2half2_rn(accO[j][2] * inv1, accO[j][3] * inv1);
        *(__half2*)(g_oc + row0 + d0) = o0;
        *(__half2*)(g_oc + row1 + d0) = o1;
    }
}

// ---------------- launch ----------------
extern "C" void kernel_launch(void* const* d_in, const int* in_sizes, int n_in,
                              void* d_out, int out_size) {
    const float* x  = (const float*)d_in[0];
    const float* Wq = (const float*)d_in[1];
    const float* bq = (const float*)d_in[2];
    const float* Wk = (const float*)d_in[3];
    const float* bk = (const float*)d_in[4];
    const float* Wv = (const float*)d_in[5];
    const float* bv = (const float*)d_in[6];
    const float* Wo = (const float*)d_in[7];
    const float* bo = (const float*)d_in[8];
    const unsigned char* mask = (const unsigned char*)d_in[9];
    float* out = (float*)d_out;

    dim3 tw(32, 8), gw(EE / 32, EE / 32);
    dim3 gg(EE / 64, MM / 128);

    cvt_x_kernel<<<MM * EE / 1024, 256>>>(x);
    cvt_mask_kernel<<<BB * SS / 256, 256>>>(mask);
    cvt_w_kernel<<<gw, tw>>>(Wq, 0);
    cvt_w_kernel<<<gw, tw>>>(Wk, 1);
    gemm_kernel<<<gg, 256>>>(0, bq, nullptr);   // launch idx 4
    gemm_kernel<<<gg, 256>>>(1, bk, nullptr);   // launch idx 5
    cvt_w_kernel<<<gw, tw>>>(Wv, 2);
    gemm_kernel<<<gg, 256>>>(2, bv, nullptr);
    cvt_w_kernel<<<gw, tw>>>(Wo, 3);
    flash_kernel<<<dim3(SS / 128, BB * HH), 256>>>();
    gemm_kernel<<<gg, 256>>>(3, bo, out);
}

// round 5
// speedup vs baseline: 1.1120x; 1.0439x over previous
#include <cuda_runtime.h>
#include <cuda_fp16.h>
#include <cstdint>

#define BB 4
#define SS 2048
#define EE 1024
#define HH 16
#define DD 64
#define MM (BB*SS)   // 8192 tokens

// ---------------- static scratch ----------------
__device__ __align__(256) __half g_xh[MM*EE];
__device__ __align__(256) __half g_wt[4][EE*EE];      // transposed [n][k]
__device__ __align__(256) __half g_q [BB*HH*SS*DD];   // [b,h,s,d]
__device__ __align__(256) __half g_k [BB*HH*SS*DD];   // [b,h,s,d]
__device__ __align__(256) __half g_vt[BB*HH*DD*SS];   // [b,h,d,s]
__device__ __align__(256) __half g_oc[MM*EE];         // [tok, h*64+d]
__device__ float  g_maskf[BB*SS];
__device__ float2 g_rope[SS*32];                      // (cos,sin) per (s, pair idx)

// ---------------- PTX helpers ----------------
__device__ __forceinline__ void mma16816(float c[4], const uint32_t a[4],
                                         uint32_t b0, uint32_t b1) {
    asm volatile(
        "mma.sync.aligned.m16n8k16.row.col.f32.f16.f16.f32 "
        "{%0,%1,%2,%3}, {%4,%5,%6,%7}, {%8,%9}, {%0,%1,%2,%3};\n"
        : "+f"(c[0]), "+f"(c[1]), "+f"(c[2]), "+f"(c[3])
        : "r"(a[0]), "r"(a[1]), "r"(a[2]), "r"(a[3]), "r"(b0), "r"(b1));
}
__device__ __forceinline__ void ldsm4(uint32_t &r0, uint32_t &r1,
                                      uint32_t &r2, uint32_t &r3, uint32_t a) {
    asm volatile("ldmatrix.sync.aligned.m8n8.x4.shared.b16 {%0,%1,%2,%3}, [%4];\n"
                 : "=r"(r0), "=r"(r1), "=r"(r2), "=r"(r3) : "r"(a));
}
__device__ __forceinline__ void cp16(void* dst, const void* src) {
    uint32_t d = (uint32_t)__cvta_generic_to_shared(dst);
    asm volatile("cp.async.cg.shared.global [%0], [%1], 16;\n" :: "r"(d), "l"(src));
}
__device__ __forceinline__ void cp_commit() { asm volatile("cp.async.commit_group;\n"); }
template<int N> __device__ __forceinline__ void cp_wait() {
    asm volatile("cp.async.wait_group %0;\n" :: "n"(N));
}

// ---------------- conversions ----------------
__global__ void cvt_x_kernel(const float* __restrict__ x) {
    int i = (blockIdx.x * blockDim.x + threadIdx.x) * 4;
    float4 v = *(const float4*)(x + i);
    __half2* o = (__half2*)(g_xh + i);
    o[0] = __floats2half2_rn(v.x, v.y);
    o[1] = __floats2half2_rn(v.z, v.w);
}
__global__ void cvt_mask_kernel(const unsigned char* __restrict__ m) {
    int i = blockIdx.x * blockDim.x + threadIdx.x;
    g_maskf[i] = m[i] ? -1e30f : 0.f;
}
__global__ void cvt_rope_kernel() {
    int i = blockIdx.x * blockDim.x + threadIdx.x;   // SS*32
    int s = i >> 5, j = i & 31;
    const float LOG2_BASE = 13.28771237954945f;      // log2(10000)
    float invf = exp2f(-(float)j * (LOG2_BASE / 32.f));
    float sn, cs;
    sincosf((float)s * invf, &sn, &cs);
    g_rope[i] = make_float2(cs, sn);
}
// W [k][n] fp32 -> g_wt[z] [n][k] fp16 (plain tiled transpose, all 4 in one grid)
__global__ void cvt_w_kernel(const float* W0, const float* W1,
                             const float* W2, const float* W3) {
    int z = blockIdx.z;
    const float* W = (z == 0) ? W0 : (z == 1) ? W1 : (z == 2) ? W2 : W3;
    __shared__ float t[32][33];
    int bx = blockIdx.x * 32, by = blockIdx.y * 32;
#pragma unroll
    for (int i = 0; i < 32; i += 8)
        t[threadIdx.y + i][threadIdx.x] = W[(by + threadIdx.y + i) * EE + bx + threadIdx.x];
    __syncthreads();
#pragma unroll
    for (int i = 0; i < 32; i += 8)
        g_wt[z][(bx + threadIdx.y + i) * EE + (by + threadIdx.x)] =
            __float2half(t[threadIdx.x][threadIdx.y + i]);
}

// ---------------- GEMM (proven round-2 core): BM=128 BN=64 BK=32 ------------
// QKV fused launch: grid (16, 64, 3), mode = blockIdx.z
// final:            grid (16, 64, 1), final_=1 -> mode 3
__global__ __launch_bounds__(256) void gemm_kernel(int final_,
                                                   const float* __restrict__ bias0,
                                                   const float* __restrict__ bias1,
                                                   const float* __restrict__ bias2,
                                                   float* __restrict__ out32) {
    int mode = final_ ? 3 : blockIdx.z;
    const float* bias = (mode == 1) ? bias1 : (mode == 2) ? bias2 : bias0;
    const __half* A  = (mode == 3) ? g_oc : g_xh;
    const __half* Bt = g_wt[mode];

    __shared__ __align__(16) __half As[2][128][40];  // pad 8 halves, 80B rows
    __shared__ __align__(16) __half Bs[2][64][40];

    int tid = threadIdx.x, w = tid >> 5, l = tid & 31, g = l >> 2, tq = l & 3;
    int bm = blockIdx.y * 128, bn = blockIdx.x * 64;

    float acc[8][4];
#pragma unroll
    for (int j = 0; j < 8; j++)
#pragma unroll
        for (int i = 0; i < 4; i++) acc[j][i] = 0.f;

    const __half* Ap = A  + (long)bm * EE;
    const __half* Bp = Bt + (long)bn * EE;
    int lr = tid >> 2, lc = (tid & 3) * 8;

    uint32_t AsB = (uint32_t)__cvta_generic_to_shared(&As[0][0][0]);
    uint32_t BsB = (uint32_t)__cvta_generic_to_shared(&Bs[0][0][0]);
    int bi = l >> 3, rin = l & 7;
    uint32_t aoff = (uint32_t)(((w * 16 + ((bi & 1) << 3) + rin) * 40 + ((bi >> 1) << 3)) * 2);
    uint32_t boff = (uint32_t)(((((bi >> 1) << 3) + rin) * 40 + ((bi & 1) << 3)) * 2);

#define GEMM_LOAD(s, k0)                                                          \
    do {                                                                          \
        cp16(&As[s][lr][lc],      Ap + (long)lr * EE + (k0) + lc);                \
        cp16(&As[s][lr + 64][lc], Ap + (long)(lr + 64) * EE + (k0) + lc);         \
        cp16(&Bs[s][lr][lc],      Bp + (long)lr * EE + (k0) + lc);                \
    } while (0)

    GEMM_LOAD(0, 0);
    cp_commit();

    for (int i = 0; i < 32; i++) {
        cp_wait<0>();
        __syncthreads();
        if (i < 31) { GEMM_LOAD((i + 1) & 1, (i + 1) * 32); cp_commit(); }
        int s = i & 1;
        uint32_t abase = AsB + s * 10240 + aoff;
        uint32_t bbase = BsB + s * 5120 + boff;
        uint32_t a[2][4];
#pragma unroll
        for (int kk = 0; kk < 2; kk++)
            ldsm4(a[kk][0], a[kk][1], a[kk][2], a[kk][3], abase + kk * 32);
#pragma unroll
        for (int jp = 0; jp < 4; jp++) {
#pragma unroll
            for (int kk = 0; kk < 2; kk++) {
                uint32_t b0, b1, b2, b3;
                ldsm4(b0, b1, b2, b3, bbase + jp * (16 * 80) + kk * 32);
                mma16816(acc[2 * jp],     a[kk], b0, b1);
                mma16816(acc[2 * jp + 1], a[kk], b2, b3);
            }
        }
    }

    // -------- epilogue (proven round-2 structure) --------
    int r0 = bm + w * 16 + g;
    int b_ = r0 >> 11;
    int s0 = r0 & 2047;
    int h  = blockIdx.x;

    if (mode == 3) {
#pragma unroll
        for (int j = 0; j < 8; j++) {
            int n = bn + j * 8 + tq * 2;
            float bv0 = bias[n], bv1 = bias[n + 1];
            float2 v0 = make_float2(acc[j][0] + bv0, acc[j][1] + bv1);
            float2 v1 = make_float2(acc[j][2] + bv0, acc[j][3] + bv1);
            *(float2*)(out32 + (long)r0 * EE + n)       = v0;
            *(float2*)(out32 + (long)(r0 + 8) * EE + n) = v1;
        }
        return;
    }

#pragma unroll
    for (int j = 0; j < 8; j++) {
        int n = bn + j * 8 + tq * 2;
        float bv0 = bias[n], bv1 = bias[n + 1];
        acc[j][0] += bv0; acc[j][1] += bv1;
        acc[j][2] += bv0; acc[j][3] += bv1;
    }

    if (mode == 2) {  // V -> [b,h,d,s]
        long base = (long)(b_ * HH + h) * DD;
#pragma unroll
        for (int j = 0; j < 8; j++) {
            int d = j * 8 + tq * 2;
            g_vt[(base + d    ) * SS + s0    ] = __float2half(acc[j][0]);
            g_vt[(base + d + 1) * SS + s0    ] = __float2half(acc[j][1]);
            g_vt[(base + d    ) * SS + s0 + 8] = __float2half(acc[j][2]);
            g_vt[(base + d + 1) * SS + s0 + 8] = __float2half(acc[j][3]);
        }
        return;
    }

    // RoPE (modes 0/1) via precomputed table; same indexing as proven sincosf path
    __half* out = (mode == 0) ? g_q : g_k;
    long rowbase = (long)(b_ * HH + h) * SS;
#pragma unroll
    for (int jp = 0; jp < 4; jp++) {
        int d = jp * 8 + tq * 2;  // x1-column index (0..30 even), pairs (d,d+32),(d+1,d+33)
#pragma unroll
        for (int rr = 0; rr < 2; rr++) {
            int s = s0 + rr * 8;
            float2 cs0 = g_rope[s * 32 + d];
            float2 cs1 = g_rope[s * 32 + d + 1];
            float x1a = acc[jp][rr * 2 + 0],     x1b = acc[jp][rr * 2 + 1];
            float x2a = acc[jp + 4][rr * 2 + 0], x2b = acc[jp + 4][rr * 2 + 1];
            __half2 lo = __floats2half2_rn(x1a * cs0.x - x2a * cs0.y,
                                           x1b * cs1.x - x2b * cs1.y);
            __half2 hi = __floats2half2_rn(x2a * cs0.x + x1a * cs0.y,
                                           x2b * cs1.x + x1b * cs1.y);
            *(__half2*)(out + (rowbase + s) * DD + d)      = lo;
            *(__half2*)(out + (rowbase + s) * DD + d + 32) = hi;
        }
    }
}

// ---------------- flash attention (proven round-2 version, verbatim) --------
__global__ __launch_bounds__(256) void flash_kernel() {
    int bh = blockIdx.y;
    int b_ = bh >> 4;
    int h  = bh & 15;
    int qt = blockIdx.x;

    __shared__ __align__(16) __half Qs[128][64];
    __shared__ __align__(16) __half Ks[2][64][64];
    __shared__ __align__(16) __half Vs[2][64][64];

    int tid = threadIdx.x, w = tid >> 5, l = tid & 31, g = l >> 2, tq = l & 3;

    const __half* Qg  = g_q  + ((long)bh * SS + qt * 128) * DD;
    const __half* Kg0 = g_k  + (long)bh * SS * DD;
    const __half* Vg0 = g_vt + (long)bh * DD * SS;

#pragma unroll
    for (int it = 0; it < 4; it++) {
        int c = tid + 256 * it, r = c >> 3, cc = c & 7;
        cp16(&Qs[r][((cc ^ (r & 7)) << 3)], Qg + r * 64 + cc * 8);
    }
    cp_commit();

#define KV_LOAD(s, t)                                                             \
    do {                                                                          \
        const __half* Kg = Kg0 + (long)(t) * 64 * DD;                             \
        const __half* Vg = Vg0 + (t) * 64;                                        \
        _Pragma("unroll")                                                         \
        for (int it = 0; it < 2; it++) {                                          \
            int c = tid + 256 * it, r = c >> 3, cc = c & 7;                       \
            cp16(&Ks[s][r][((cc ^ (r & 7)) << 3)], Kg + r * 64 + cc * 8);         \
            cp16(&Vs[s][r][((cc ^ (r & 7)) << 3)], Vg + (long)r * SS + cc * 8);   \
        }                                                                         \
    } while (0)

    KV_LOAD(0, 0);
    cp_commit();

    uint32_t QsB = (uint32_t)__cvta_generic_to_shared(&Qs[0][0]);
    uint32_t KsB = (uint32_t)__cvta_generic_to_shared(&Ks[0][0][0]);
    uint32_t VsB = (uint32_t)__cvta_generic_to_shared(&Vs[0][0][0]);
    int bi = l >> 3, rin = l & 7;

    cp_wait<1>();
    __syncthreads();

    uint32_t qf[4][4];
    {
        uint32_t qrowb = QsB + (uint32_t)((w * 16 + ((bi & 1) << 3) + rin) * 128);
        int qcb = bi >> 1;
#pragma unroll
        for (int kk = 0; kk < 4; kk++)
            ldsm4(qf[kk][0], qf[kk][1], qf[kk][2], qf[kk][3],
                  qrowb + (uint32_t)((((kk * 2 + qcb) ^ rin) << 4)));
    }

    uint32_t kvro = (uint32_t)(((((bi >> 1) << 3) + rin)) * 128);
    int kcb = bi & 1;

    float accO[8][4];
#pragma unroll
    for (int j = 0; j < 8; j++)
#pragma unroll
        for (int i = 0; i < 4; i++) accO[j][i] = 0.f;
    float mi0 = -1e30f, mi1 = -1e30f, li0 = 0.f, li1 = 0.f;

    const float* mrow = g_maskf + b_ * SS;

    for (int t = 0; t < SS / 64; t++) {
        cp_wait<0>();
        __syncthreads();
        if (t < SS / 64 - 1) { KV_LOAD((t + 1) & 1, t + 1); cp_commit(); }
        int s = t & 1;
        uint32_t kbase = KsB + s * 8192 + kvro;
        uint32_t vbase = VsB + s * 8192 + kvro;

        float sc[8][4];
#pragma unroll
        for (int j = 0; j < 8; j++)
#pragma unroll
            for (int i = 0; i < 4; i++) sc[j][i] = 0.f;
#pragma unroll
        for (int kk = 0; kk < 4; kk++) {
#pragma unroll
            for (int jp = 0; jp < 4; jp++) {
                uint32_t b0, b1, b2, b3;
                ldsm4(b0, b1, b2, b3, kbase + jp * 2048 + ((((kk * 2 + kcb) ^ rin)) << 4));
                mma16816(sc[2 * jp],     qf[kk], b0, b1);
                mma16816(sc[2 * jp + 1], qf[kk], b2, b3);
            }
        }
#pragma unroll
        for (int j = 0; j < 8; j++) {
            float2 mv = *(const float2*)(mrow + t * 64 + j * 8 + tq * 2);
            sc[j][0] = sc[j][0] * 0.125f + mv.x;
            sc[j][1] = sc[j][1] * 0.125f + mv.y;
            sc[j][2] = sc[j][2] * 0.125f + mv.x;
            sc[j][3] = sc[j][3] * 0.125f + mv.y;
        }
        float mx0 = -1e30f, mx1 = -1e30f;
#pragma unroll
        for (int j = 0; j < 8; j++) {
            mx0 = fmaxf(mx0, fmaxf(sc[j][0], sc[j][1]));
            mx1 = fmaxf(mx1, fmaxf(sc[j][2], sc[j][3]));
        }
        mx0 = fmaxf(mx0, __shfl_xor_sync(0xffffffff, mx0, 1));
        mx0 = fmaxf(mx0, __shfl_xor_sync(0xffffffff, mx0, 2));
        mx1 = fmaxf(mx1, __shfl_xor_sync(0xffffffff, mx1, 1));
        mx1 = fmaxf(mx1, __shfl_xor_sync(0xffffffff, mx1, 2));
        float mn0 = fmaxf(mi0, mx0), mn1 = fmaxf(mi1, mx1);
        float rs0f = __expf(mi0 - mn0), rs1f = __expf(mi1 - mn1);
        mi0 = mn0; mi1 = mn1;

        uint32_t pa[4][4];
        float sum0 = 0.f, sum1 = 0.f;
#pragma unroll
        for (int j = 0; j < 8; j++) {
            float p0 = __expf(sc[j][0] - mn0), p1 = __expf(sc[j][1] - mn0);
            float p2 = __expf(sc[j][2] - mn1), p3 = __expf(sc[j][3] - mn1);
            sum0 += p0 + p1; sum1 += p2 + p3;
            __half2 h01 = __floats2half2_rn(p0, p1);
            __half2 h23 = __floats2half2_rn(p2, p3);
            int kk = j >> 1;
            if ((j & 1) == 0) { pa[kk][0] = *(uint32_t*)&h01; pa[kk][1] = *(uint32_t*)&h23; }
            else             { pa[kk][2] = *(uint32_t*)&h01; pa[kk][3] = *(uint32_t*)&h23; }
        }
        sum0 += __shfl_xor_sync(0xffffffff, sum0, 1);
        sum0 += __shfl_xor_sync(0xffffffff, sum0, 2);
        sum1 += __shfl_xor_sync(0xffffffff, sum1, 1);
        sum1 += __shfl_xor_sync(0xffffffff, sum1, 2);
        li0 = li0 * rs0f + sum0;
        li1 = li1 * rs1f + sum1;
#pragma unroll
        for (int j = 0; j < 8; j++) {
            accO[j][0] *= rs0f; accO[j][1] *= rs0f;
            accO[j][2] *= rs1f; accO[j][3] *= rs1f;
        }
#pragma unroll
        for (int kk = 0; kk < 4; kk++) {
#pragma unroll
            for (int jp = 0; jp < 4; jp++) {
                uint32_t b0, b1, b2, b3;
                ldsm4(b0, b1, b2, b3, vbase + jp * 2048 + ((((kk * 2 + kcb) ^ rin)) << 4));
                mma16816(accO[2 * jp],     pa[kk], b0, b1);
                mma16816(accO[2 * jp + 1], pa[kk], b2, b3);
            }
        }
    }

    float inv0 = 1.f / li0, inv1 = 1.f / li1;
    int q0 = qt * 128 + w * 16 + g;
    long row0 = (long)(b_ * SS + q0) * EE + h * 64;
    long row1 = (long)(b_ * SS + q0 + 8) * EE + h * 64;
#pragma unroll
    for (int j = 0; j < 8; j++) {
        int d0 = j * 8 + tq * 2;
        __half2 o0 = __floats2half2_rn(accO[j][0] * inv0, accO[j][1] * inv0);
        __half2 o1 = __floats2half2_rn(accO[j][2] * inv1, accO[j][3] * inv1);
        *(__half2*)(g_oc + row0 + d0) = o0;
        *(__half2*)(g_oc + row1 + d0) = o1;
    }
}

// ---------------- launch ----------------
extern "C" void kernel_launch(void* const* d_in, const int* in_sizes, int n_in,
                              void* d_out, int out_size) {
    const float* x  = (const float*)d_in[0];
    const float* Wq = (const float*)d_in[1];
    const float* bq = (const float*)d_in[2];
    const float* Wk = (const float*)d_in[3];
    const float* bk = (const float*)d_in[4];
    const float* Wv = (const float*)d_in[5];
    const float* bv = (const float*)d_in[6];
    const float* Wo = (const float*)d_in[7];
    const float* bo = (const float*)d_in[8];
    const unsigned char* mask = (const unsigned char*)d_in[9];
    float* out = (float*)d_out;

    cvt_x_kernel<<<MM * EE / 1024, 256>>>(x);                          // 0
    cvt_w_kernel<<<dim3(32, 32, 4), dim3(32, 8)>>>(Wq, Wk, Wv, Wo);    // 1
    cvt_mask_kernel<<<BB * SS / 256, 256>>>(mask);                     // 2
    cvt_rope_kernel<<<SS * 32 / 256, 256>>>();                         // 3

    gemm_kernel<<<dim3(EE / 64, MM / 128, 3), 256>>>(0, bq, bk, bv, nullptr); // 4 (QKV fused)
    flash_kernel<<<dim3(SS / 128, BB * HH), 256>>>();                          // 5 (ncu target)
    gemm_kernel<<<dim3(EE / 64, MM / 128, 1), 256>>>(1, bo, bo, bo, out);      // 6
}

// round 7
// speedup vs baseline: 1.8015x; 1.6200x over previous
#include <cuda_runtime.h>
#include <cuda_fp16.h>
#include <cstdint>

#define BB 4
#define SS 2048
#define EE 1024
#define HH 16
#define DD 64
#define MM (BB*SS)   // 8192 tokens

// ---------------- static scratch ----------------
__device__ __align__(256) __half g_xh[MM*EE];
__device__ __align__(256) __half g_wt[4][EE*EE];      // transposed [n][k]
__device__ __align__(256) __half g_q [BB*HH*SS*DD];   // [b,h,s,d]
__device__ __align__(256) __half g_k [BB*HH*SS*DD];   // [b,h,s,d]
__device__ __align__(256) __half g_vt[BB*HH*DD*SS];   // [b,h,d,s]
__device__ __align__(256) __half g_oc[MM*EE];         // [tok, h*64+d]
__device__ float  g_maskf[BB*SS];
__device__ float2 g_rope[SS*32];                      // (cos,sin) per (s, pair idx)

// ---------------- PTX helpers ----------------
__device__ __forceinline__ void mma16816(float c[4], const uint32_t a[4],
                                         uint32_t b0, uint32_t b1) {
    asm volatile(
        "mma.sync.aligned.m16n8k16.row.col.f32.f16.f16.f32 "
        "{%0,%1,%2,%3}, {%4,%5,%6,%7}, {%8,%9}, {%0,%1,%2,%3};\n"
        : "+f"(c[0]), "+f"(c[1]), "+f"(c[2]), "+f"(c[3])
        : "r"(a[0]), "r"(a[1]), "r"(a[2]), "r"(a[3]), "r"(b0), "r"(b1));
}
__device__ __forceinline__ void ldsm4(uint32_t &r0, uint32_t &r1,
                                      uint32_t &r2, uint32_t &r3, uint32_t a) {
    asm volatile("ldmatrix.sync.aligned.m8n8.x4.shared.b16 {%0,%1,%2,%3}, [%4];\n"
                 : "=r"(r0), "=r"(r1), "=r"(r2), "=r"(r3) : "r"(a));
}
__device__ __forceinline__ void cp16(void* dst, const void* src) {
    uint32_t d = (uint32_t)__cvta_generic_to_shared(dst);
    asm volatile("cp.async.cg.shared.global [%0], [%1], 16;\n" :: "r"(d), "l"(src));
}
__device__ __forceinline__ void cp_commit() { asm volatile("cp.async.commit_group;\n"); }
template<int N> __device__ __forceinline__ void cp_wait() {
    asm volatile("cp.async.wait_group %0;\n" :: "n"(N));
}
__device__ __forceinline__ uint32_t h2exp2(uint32_t x) {
    uint32_t r;
    asm volatile("ex2.approx.f16x2 %0, %1;\n" : "=r"(r) : "r"(x));
    return r;
}

// ---------------- conversions ----------------
__global__ void cvt_x_kernel(const float* __restrict__ x) {
    int i = (blockIdx.x * blockDim.x + threadIdx.x) * 4;
    float4 v = *(const float4*)(x + i);
    __half2* o = (__half2*)(g_xh + i);
    o[0] = __floats2half2_rn(v.x, v.y);
    o[1] = __floats2half2_rn(v.z, v.w);
}
// W [k][n] fp32 -> g_wt[z] [n][k] fp16
__global__ void cvt_w_kernel(const float* W0, const float* W1,
                             const float* W2, const float* W3) {
    int z = blockIdx.z;
    const float* W = (z == 0) ? W0 : (z == 1) ? W1 : (z == 2) ? W2 : W3;
    __shared__ float t[32][33];
    int bx = blockIdx.x * 32, by = blockIdx.y * 32;
#pragma unroll
    for (int i = 0; i < 32; i += 8)
        t[threadIdx.y + i][threadIdx.x] = W[(by + threadIdx.y + i) * EE + bx + threadIdx.x];
    __syncthreads();
#pragma unroll
    for (int i = 0; i < 32; i += 8)
        g_wt[z][(bx + threadIdx.y + i) * EE + (by + threadIdx.x)] =
            __float2half(t[threadIdx.x][threadIdx.y + i]);
}
// rope table + mask in one launch (keeps GEMM at launch idx 3 for ncu)
__global__ void cvt_misc_kernel(const unsigned char* __restrict__ m) {
    int i = blockIdx.x * blockDim.x + threadIdx.x;   // SS*32 = 65536
    int s = i >> 5, j = i & 31;
    const float LOG2_BASE = 13.28771237954945f;      // log2(10000)
    float invf = exp2f(-(float)j * (LOG2_BASE / 32.f));
    float sn, cs;
    sincosf((float)s * invf, &sn, &cs);
    g_rope[i] = make_float2(cs, sn);
    if (i < BB * SS) g_maskf[i] = m[i] ? -1e30f : 0.f;
}

// ---------------- GEMM (proven core): BM=128 BN=64 BK=32 --------------------
__global__ __launch_bounds__(256) void gemm_kernel(int final_,
                                                   const float* __restrict__ bias0,
                                                   const float* __restrict__ bias1,
                                                   const float* __restrict__ bias2,
                                                   float* __restrict__ out32) {
    int mode = final_ ? 3 : blockIdx.z;
    const float* bias = (mode == 1) ? bias1 : (mode == 2) ? bias2 : bias0;
    const __half* A  = (mode == 3) ? g_oc : g_xh;
    const __half* Bt = g_wt[mode];

    __shared__ __align__(16) __half As[2][128][40];
    __shared__ __align__(16) __half Bs[2][64][40];

    int tid = threadIdx.x, w = tid >> 5, l = tid & 31, g = l >> 2, tq = l & 3;
    int bm = blockIdx.y * 128, bn = blockIdx.x * 64;

    float acc[8][4];
#pragma unroll
    for (int j = 0; j < 8; j++)
#pragma unroll
        for (int i = 0; i < 4; i++) acc[j][i] = 0.f;

    const __half* Ap = A  + (long)bm * EE;
    const __half* Bp = Bt + (long)bn * EE;
    int lr = tid >> 2, lc = (tid & 3) * 8;

    uint32_t AsB = (uint32_t)__cvta_generic_to_shared(&As[0][0][0]);
    uint32_t BsB = (uint32_t)__cvta_generic_to_shared(&Bs[0][0][0]);
    int bi = l >> 3, rin = l & 7;
    uint32_t aoff = (uint32_t)(((w * 16 + ((bi & 1) << 3) + rin) * 40 + ((bi >> 1) << 3)) * 2);
    uint32_t boff = (uint32_t)(((((bi >> 1) << 3) + rin) * 40 + ((bi & 1) << 3)) * 2);

#define GEMM_LOAD(s, k0)                                                          \
    do {                                                                          \
        cp16(&As[s][lr][lc],      Ap + (long)lr * EE + (k0) + lc);                \
        cp16(&As[s][lr + 64][lc], Ap + (long)(lr + 64) * EE + (k0) + lc);         \
        cp16(&Bs[s][lr][lc],      Bp + (long)lr * EE + (k0) + lc);                \
    } while (0)

    GEMM_LOAD(0, 0);
    cp_commit();

    for (int i = 0; i < 32; i++) {
        cp_wait<0>();
        __syncthreads();
        if (i < 31) { GEMM_LOAD((i + 1) & 1, (i + 1) * 32); cp_commit(); }
        int s = i & 1;
        uint32_t abase = AsB + s * 10240 + aoff;
        uint32_t bbase = BsB + s * 5120 + boff;
        uint32_t a[2][4];
#pragma unroll
        for (int kk = 0; kk < 2; kk++)
            ldsm4(a[kk][0], a[kk][1], a[kk][2], a[kk][3], abase + kk * 32);
#pragma unroll
        for (int jp = 0; jp < 4; jp++) {
#pragma unroll
            for (int kk = 0; kk < 2; kk++) {
                uint32_t b0, b1, b2, b3;
                ldsm4(b0, b1, b2, b3, bbase + jp * (16 * 80) + kk * 32);
                mma16816(acc[2 * jp],     a[kk], b0, b1);
                mma16816(acc[2 * jp + 1], a[kk], b2, b3);
            }
        }
    }

    int r0 = bm + w * 16 + g;
    int b_ = r0 >> 11;
    int s0 = r0 & 2047;
    int h  = blockIdx.x;

    if (mode == 3) {
#pragma unroll
        for (int j = 0; j < 8; j++) {
            int n = bn + j * 8 + tq * 2;
            float bv0 = bias[n], bv1 = bias[n + 1];
            float2 v0 = make_float2(acc[j][0] + bv0, acc[j][1] + bv1);
            float2 v1 = make_float2(acc[j][2] + bv0, acc[j][3] + bv1);
            *(float2*)(out32 + (long)r0 * EE + n)       = v0;
            *(float2*)(out32 + (long)(r0 + 8) * EE + n) = v1;
        }
        return;
    }

#pragma unroll
    for (int j = 0; j < 8; j++) {
        int n = bn + j * 8 + tq * 2;
        float bv0 = bias[n], bv1 = bias[n + 1];
        acc[j][0] += bv0; acc[j][1] += bv1;
        acc[j][2] += bv0; acc[j][3] += bv1;
    }

    if (mode == 2) {  // V -> [b,h,d,s]
        long base = (long)(b_ * HH + h) * DD;
#pragma unroll
        for (int j = 0; j < 8; j++) {
            int d = j * 8 + tq * 2;
            g_vt[(base + d    ) * SS + s0    ] = __float2half(acc[j][0]);
            g_vt[(base + d + 1) * SS + s0    ] = __float2half(acc[j][1]);
            g_vt[(base + d    ) * SS + s0 + 8] = __float2half(acc[j][2]);
            g_vt[(base + d + 1) * SS + s0 + 8] = __float2half(acc[j][3]);
        }
        return;
    }

    // RoPE (modes 0/1) via table
    __half* out = (mode == 0) ? g_q : g_k;
    long rowbase = (long)(b_ * HH + h) * SS;
#pragma unroll
    for (int jp = 0; jp < 4; jp++) {
        int d = jp * 8 + tq * 2;
#pragma unroll
        for (int rr = 0; rr < 2; rr++) {
            int s = s0 + rr * 8;
            float2 cs0 = g_rope[s * 32 + d];
            float2 cs1 = g_rope[s * 32 + d + 1];
            float x1a = acc[jp][rr * 2 + 0],     x1b = acc[jp][rr * 2 + 1];
            float x2a = acc[jp + 4][rr * 2 + 0], x2b = acc[jp + 4][rr * 2 + 1];
            __half2 lo = __floats2half2_rn(x1a * cs0.x - x2a * cs0.y,
                                           x1b * cs1.x - x2b * cs1.y);
            __half2 hi = __floats2half2_rn(x2a * cs0.x + x1a * cs0.y,
                                           x2b * cs1.x + x1b * cs1.y);
            *(__half2*)(out + (rowbase + s) * DD + d)      = lo;
            *(__half2*)(out + (rowbase + s) * DD + d + 32) = hi;
        }
    }
}

// ---------------- flash attention: log2-softmax + f16x2 ex2 + mma row-sum ---
__global__ __launch_bounds__(256) void flash_kernel() {
    int bh = blockIdx.y;
    int b_ = bh >> 4;
    int h  = bh & 15;
    int qt = blockIdx.x;

    __shared__ __align__(16) __half Qs[128][64];
    __shared__ __align__(16) __half Ks[2][64][64];
    __shared__ __align__(16) __half Vs[2][64][64];

    int tid = threadIdx.x, w = tid >> 5, l = tid & 31, g = l >> 2, tq = l & 3;

    const __half* Qg  = g_q  + ((long)bh * SS + qt * 128) * DD;
    const __half* Kg0 = g_k  + (long)bh * SS * DD;
    const __half* Vg0 = g_vt + (long)bh * DD * SS;

#pragma unroll
    for (int it = 0; it < 4; it++) {
        int c = tid + 256 * it, r = c >> 3, cc = c & 7;
        cp16(&Qs[r][((cc ^ (r & 7)) << 3)], Qg + r * 64 + cc * 8);
    }
    cp_commit();

#define KV_LOAD(s, t)                                                             \
    do {                                                                          \
        const __half* Kg = Kg0 + (long)(t) * 64 * DD;                             \
        const __half* Vg = Vg0 + (t) * 64;                                        \
        _Pragma("unroll")                                                         \
        for (int it = 0; it < 2; it++) {                                          \
            int c = tid + 256 * it, r = c >> 3, cc = c & 7;                       \
            cp16(&Ks[s][r][((cc ^ (r & 7)) << 3)], Kg + r * 64 + cc * 8);         \
            cp16(&Vs[s][r][((cc ^ (r & 7)) << 3)], Vg + (long)r * SS + cc * 8);   \
        }                                                                         \
    } while (0)

    KV_LOAD(0, 0);
    cp_commit();

    uint32_t QsB = (uint32_t)__cvta_generic_to_shared(&Qs[0][0]);
    uint32_t KsB = (uint32_t)__cvta_generic_to_shared(&Ks[0][0][0]);
    uint32_t VsB = (uint32_t)__cvta_generic_to_shared(&Vs[0][0][0]);
    int bi = l >> 3, rin = l & 7;

    cp_wait<1>();
    __syncthreads();

    uint32_t qf[4][4];
    {
        uint32_t qrowb = QsB + (uint32_t)((w * 16 + ((bi & 1) << 3) + rin) * 128);
        int qcb = bi >> 1;
#pragma unroll
        for (int kk = 0; kk < 4; kk++)
            ldsm4(qf[kk][0], qf[kk][1], qf[kk][2], qf[kk][3],
                  qrowb + (uint32_t)((((kk * 2 + qcb) ^ rin) << 4)));
    }

    uint32_t kvro = (uint32_t)(((((bi >> 1) << 3) + rin)) * 128);
    int kcb = bi & 1;

    float accO[8][4];
#pragma unroll
    for (int j = 0; j < 8; j++)
#pragma unroll
        for (int i = 0; i < 4; i++) accO[j][i] = 0.f;
    float mi0 = -1e30f, mi1 = -1e30f, li0 = 0.f, li1 = 0.f;

    const float* mrow = g_maskf + b_ * SS;
    const float SCALE2 = 0.18033688011112536f;   // 1/8 * log2(e)
    const uint32_t ONES = 0x3C003C00u;           // half2(1,1)

    for (int t = 0; t < SS / 64; t++) {
        cp_wait<0>();
        __syncthreads();
        if (t < SS / 64 - 1) { KV_LOAD((t + 1) & 1, t + 1); cp_commit(); }
        int s = t & 1;
        uint32_t kbase = KsB + s * 8192 + kvro;
        uint32_t vbase = VsB + s * 8192 + kvro;

        // S = Q @ K^T
        float sc[8][4];
#pragma unroll
        for (int j = 0; j < 8; j++)
#pragma unroll
            for (int i = 0; i < 4; i++) sc[j][i] = 0.f;
#pragma unroll
        for (int kk = 0; kk < 4; kk++) {
#pragma unroll
            for (int jp = 0; jp < 4; jp++) {
                uint32_t b0, b1, b2, b3;
                ldsm4(b0, b1, b2, b3, kbase + jp * 2048 + ((((kk * 2 + kcb) ^ rin)) << 4));
                mma16816(sc[2 * jp],     qf[kk], b0, b1);
                mma16816(sc[2 * jp + 1], qf[kk], b2, b3);
            }
        }
        // scale + mask in log2 domain
#pragma unroll
        for (int j = 0; j < 8; j++) {
            float2 mv = *(const float2*)(mrow + t * 64 + j * 8 + tq * 2);
            sc[j][0] = sc[j][0] * SCALE2 + mv.x;
            sc[j][1] = sc[j][1] * SCALE2 + mv.y;
            sc[j][2] = sc[j][2] * SCALE2 + mv.x;
            sc[j][3] = sc[j][3] * SCALE2 + mv.y;
        }
        // row max (log2 domain)
        float mx0 = -1e30f, mx1 = -1e30f;
#pragma unroll
        for (int j = 0; j < 8; j++) {
            mx0 = fmaxf(mx0, fmaxf(sc[j][0], sc[j][1]));
            mx1 = fmaxf(mx1, fmaxf(sc[j][2], sc[j][3]));
        }
        mx0 = fmaxf(mx0, __shfl_xor_sync(0xffffffff, mx0, 1));
        mx0 = fmaxf(mx0, __shfl_xor_sync(0xffffffff, mx0, 2));
        mx1 = fmaxf(mx1, __shfl_xor_sync(0xffffffff, mx1, 1));
        mx1 = fmaxf(mx1, __shfl_xor_sync(0xffffffff, mx1, 2));
        float mn0 = fmaxf(mi0, mx0), mn1 = fmaxf(mi1, mx1);
        float rs0f = exp2f(mi0 - mn0), rs1f = exp2f(mi1 - mn1);
        mi0 = mn0; mi1 = mn1;

        // P = 2^(S - m): convert pairs to f16x2, one ex2.approx.f16x2 per pair
        uint32_t pa[4][4];
#pragma unroll
        for (int j = 0; j < 8; j++) {
            __half2 h01 = __floats2half2_rn(sc[j][0] - mn0, sc[j][1] - mn0);
            __half2 h23 = __floats2half2_rn(sc[j][2] - mn1, sc[j][3] - mn1);
            uint32_t p01 = h2exp2(*(uint32_t*)&h01);
            uint32_t p23 = h2exp2(*(uint32_t*)&h23);
            int kk = j >> 1;
            if ((j & 1) == 0) { pa[kk][0] = p01; pa[kk][1] = p23; }
            else             { pa[kk][2] = p01; pa[kk][3] = p23; }
        }
        // row sums via tensor core (B = ones)
        float accS[4] = {0.f, 0.f, 0.f, 0.f};
#pragma unroll
        for (int kk = 0; kk < 4; kk++)
            mma16816(accS, pa[kk], ONES, ONES);
        li0 = li0 * rs0f + accS[0];
        li1 = li1 * rs1f + accS[2];
#pragma unroll
        for (int j = 0; j < 8; j++) {
            accO[j][0] *= rs0f; accO[j][1] *= rs0f;
            accO[j][2] *= rs1f; accO[j][3] *= rs1f;
        }
        // O += P @ V
#pragma unroll
        for (int kk = 0; kk < 4; kk++) {
#pragma unroll
            for (int jp = 0; jp < 4; jp++) {
                uint32_t b0, b1, b2, b3;
                ldsm4(b0, b1, b2, b3, vbase + jp * 2048 + ((((kk * 2 + kcb) ^ rin)) << 4));
                mma16816(accO[2 * jp],     pa[kk], b0, b1);
                mma16816(accO[2 * jp + 1], pa[kk], b2, b3);
            }
        }
    }

    float inv0 = 1.f / li0, inv1 = 1.f / li1;
    int q0 = qt * 128 + w * 16 + g;
    long row0 = (long)(b_ * SS + q0) * EE + h * 64;
    long row1 = (long)(b_ * SS + q0 + 8) * EE + h * 64;
#pragma unroll
    for (int j = 0; j < 8; j++) {
        int d0 = j * 8 + tq * 2;
        __half2 o0 = __floats2half2_rn(accO[j][0] * inv0, accO[j][1] * inv0);
        __half2 o1 = __floats2half2_rn(accO[j][2] * inv1, accO[j][3] * inv1);
        *(__half2*)(g_oc + row0 + d0) = o0;
        *(__half2*)(g_oc + row1 + d0) = o1;
    }
}

// ---------------- launch ----------------
extern "C" void kernel_launch(void* const* d_in, const int* in_sizes, int n_in,
                              void* d_out, int out_size) {
    const float* x  = (const float*)d_in[0];
    const float* Wq = (const float*)d_in[1];
    const float* bq = (const float*)d_in[2];
    const float* Wk = (const float*)d_in[3];
    const float* bk = (const float*)d_in[4];
    const float* Wv = (const float*)d_in[5];
    const float* bv = (const float*)d_in[6];
    const float* Wo = (const float*)d_in[7];
    const float* bo = (const float*)d_in[8];
    const unsigned char* mask = (const unsigned char*)d_in[9];
    float* out = (float*)d_out;

    cvt_x_kernel<<<MM * EE / 1024, 256>>>(x);                              // 0
    cvt_w_kernel<<<dim3(32, 32, 4), dim3(32, 8)>>>(Wq, Wk, Wv, Wo);        // 1
    cvt_misc_kernel<<<SS * 32 / 256, 256>>>(mask);                         // 2

    gemm_kernel<<<dim3(EE / 64, MM / 128, 3), 256>>>(0, bq, bk, bv, nullptr); // 3 (QKV, ncu)
    flash_kernel<<<dim3(SS / 128, BB * HH), 256>>>();                          // 4
    gemm_kernel<<<dim3(EE / 64, MM / 128, 1), 256>>>(1, bo, bo, bo, out);      // 5
}

// round 9
// speedup vs baseline: 1.9529x; 1.0841x over previous
#include <cuda_runtime.h>
#include <cuda_fp16.h>
#include <cstdint>

#define BB 4
#define SS 2048
#define EE 1024
#define HH 16
#define DD 64
#define MM (BB*SS)   // 8192 tokens

// ---------------- static scratch ----------------
__device__ __align__(256) __half g_xh[MM*EE];
__device__ __align__(256) __half g_wt[4][EE*EE];      // transposed [n][k] (NO permutation)
__device__ __align__(256) __half g_q [BB*HH*SS*DD];   // [b,h,s,d]
__device__ __align__(256) __half g_k [BB*HH*SS*DD];   // [b,h,s,d]
__device__ __align__(256) __half g_vt[BB*HH*DD*SS];   // [b,h,d,s]
__device__ __align__(256) __half g_oc[MM*EE];         // [tok, h*64+d]
__device__ float  g_maskf[BB*SS];
__device__ float2 g_rope[SS*32];                      // (cos,sin) per (s, pair idx)

// ---------------- PTX helpers ----------------
__device__ __forceinline__ void mma16816(float c[4], const uint32_t a[4],
                                         uint32_t b0, uint32_t b1) {
    asm volatile(
        "mma.sync.aligned.m16n8k16.row.col.f32.f16.f16.f32 "
        "{%0,%1,%2,%3}, {%4,%5,%6,%7}, {%8,%9}, {%0,%1,%2,%3};\n"
        : "+f"(c[0]), "+f"(c[1]), "+f"(c[2]), "+f"(c[3])
        : "r"(a[0]), "r"(a[1]), "r"(a[2]), "r"(a[3]), "r"(b0), "r"(b1));
}
__device__ __forceinline__ void ldsm4(uint32_t &r0, uint32_t &r1,
                                      uint32_t &r2, uint32_t &r3, uint32_t a) {
    asm volatile("ldmatrix.sync.aligned.m8n8.x4.shared.b16 {%0,%1,%2,%3}, [%4];\n"
                 : "=r"(r0), "=r"(r1), "=r"(r2), "=r"(r3) : "r"(a));
}
__device__ __forceinline__ void cp16(void* dst, const void* src) {
    uint32_t d = (uint32_t)__cvta_generic_to_shared(dst);
    asm volatile("cp.async.cg.shared.global [%0], [%1], 16;\n" :: "r"(d), "l"(src));
}
__device__ __forceinline__ void cp_commit() { asm volatile("cp.async.commit_group;\n"); }
template<int N> __device__ __forceinline__ void cp_wait() {
    asm volatile("cp.async.wait_group %0;\n" :: "n"(N));
}
__device__ __forceinline__ uint32_t h2exp2(uint32_t x) {
    uint32_t r;
    asm volatile("ex2.approx.f16x2 %0, %1;\n" : "=r"(r) : "r"(x));
    return r;
}

// ---------------- conversions ----------------
__global__ void cvt_x_misc_kernel(const float* __restrict__ x,
                                  const unsigned char* __restrict__ m) {
    if (blockIdx.x < MM * EE / 1024) {
        int i = (blockIdx.x * blockDim.x + threadIdx.x) * 4;
        float4 v = *(const float4*)(x + i);
        __half2* o = (__half2*)(g_xh + i);
        o[0] = __floats2half2_rn(v.x, v.y);
        o[1] = __floats2half2_rn(v.z, v.w);
    } else {
        int i = (blockIdx.x - MM * EE / 1024) * blockDim.x + threadIdx.x;  // SS*32
        int s = i >> 5, j = i & 31;
        const float LOG2_BASE = 13.28771237954945f;   // log2(10000)
        float invf = exp2f(-(float)j * (LOG2_BASE / 32.f));
        float sn, cs;
        sincosf((float)s * invf, &sn, &cs);
        g_rope[i] = make_float2(cs, sn);
        if (i < BB * SS) g_maskf[i] = m[i] ? -1e30f : 0.f;
    }
}
// W [k][n] fp32 -> g_wt[z] [n][k] fp16 (plain transpose, NO permutation)
__global__ void cvt_w_kernel(const float* W0, const float* W1,
                             const float* W2, const float* W3) {
    int z = blockIdx.z;
    const float* W = (z == 0) ? W0 : (z == 1) ? W1 : (z == 2) ? W2 : W3;
    __shared__ float t[32][33];
    int bx = blockIdx.x * 32, by = blockIdx.y * 32;
#pragma unroll
    for (int i = 0; i < 32; i += 8)
        t[threadIdx.y + i][threadIdx.x] = W[(by + threadIdx.y + i) * EE + bx + threadIdx.x];
    __syncthreads();
#pragma unroll
    for (int i = 0; i < 32; i += 8)
        g_wt[z][(bx + threadIdx.y + i) * EE + (by + threadIdx.x)] =
            __float2half(t[threadIdx.x][threadIdx.y + i]);
}

// ---------------- GEMM: BM=128 BN=128 BK=32, 256 thr, 2-stage wait<0> -------
// Warp layout: wm = w>>2 (2 M-halves of 64), wn = w&3.
// Warp wn covers B n-rows {base..base+15} U {base+32..base+47},
// base = (wn>>1)*64 + (wn&1)*16 -> acc[mt][jn] & acc[mt][jn+2] are RoPE pairs.
__global__ __launch_bounds__(256) void gemm_kernel(int final_,
                                                   const float* __restrict__ bias0,
                                                   const float* __restrict__ bias1,
                                                   const float* __restrict__ bias2,
                                                   float* __restrict__ out32) {
    int mode = final_ ? 3 : blockIdx.z;
    const float* bias = (mode == 1) ? bias1 : (mode == 2) ? bias2 : bias0;
    const __half* A  = (mode == 3) ? g_oc : g_xh;
    const __half* Bw = g_wt[mode];

    __shared__ __align__(16) __half As[2][128][40];   // 20480 B
    __shared__ __align__(16) __half Bs[2][128][40];   // 20480 B

    int tid = threadIdx.x, w = tid >> 5, l = tid & 31;
    int wm = w >> 2, wn = w & 3, g = l >> 2, tq = l & 3;
    int bi = l >> 3, rin = l & 7;
    int bm = blockIdx.y * 128, bn = blockIdx.x * 128;
    int nb = (wn >> 1) * 64 + (wn & 1) * 16;          // warp B-row base

    float acc[4][4][4];
#pragma unroll
    for (int mt = 0; mt < 4; mt++)
#pragma unroll
        for (int jn = 0; jn < 4; jn++)
#pragma unroll
            for (int i = 0; i < 4; i++) acc[mt][jn][i] = 0.f;

    const __half* Ap = A  + (long)bm * EE;
    const __half* Bp = Bw + (long)bn * EE;
    int lr = tid >> 2, lc = (tid & 3) * 8;

    uint32_t AsB = (uint32_t)__cvta_generic_to_shared(&As[0][0][0]);
    uint32_t BsB = (uint32_t)__cvta_generic_to_shared(&Bs[0][0][0]);
    uint32_t aoff = (uint32_t)(((wm * 64 + ((bi & 1) << 3) + rin) * 40 + ((bi >> 1) << 3)) * 2);
    uint32_t boff = (uint32_t)(((nb + ((bi >> 1) << 3) + rin) * 40 + ((bi & 1) << 3)) * 2);

#define GEMM_LOAD(s, k0)                                                          \
    do {                                                                          \
        cp16(&As[s][lr][lc],      Ap + (long)lr * EE + (k0) + lc);                \
        cp16(&As[s][lr + 64][lc], Ap + (long)(lr + 64) * EE + (k0) + lc);         \
        cp16(&Bs[s][lr][lc],      Bp + (long)lr * EE + (k0) + lc);                \
        cp16(&Bs[s][lr + 64][lc], Bp + (long)(lr + 64) * EE + (k0) + lc);         \
    } while (0)

    GEMM_LOAD(0, 0);
    cp_commit();

    for (int i = 0; i < 32; i++) {
        cp_wait<0>();                 // fully drained: zero race surface (proven)
        __syncthreads();
        if (i < 31) { GEMM_LOAD((i + 1) & 1, (i + 1) * 32); cp_commit(); }
        int s = i & 1;
        uint32_t abase = AsB + s * 10240 + aoff;
        uint32_t bbase = BsB + s * 10240 + boff;
#pragma unroll
        for (int kk = 0; kk < 2; kk++) {
            uint32_t a[4][4];
#pragma unroll
            for (int mt = 0; mt < 4; mt++)
                ldsm4(a[mt][0], a[mt][1], a[mt][2], a[mt][3], abase + mt * 1280 + kk * 32);
#pragma unroll
            for (int jp = 0; jp < 2; jp++) {      // jp block at n-rows nb + jp*32
                uint32_t b0, b1, b2, b3;
                ldsm4(b0, b1, b2, b3, bbase + jp * 2560 + kk * 32);
#pragma unroll
                for (int mt = 0; mt < 4; mt++) {
                    mma16816(acc[mt][2 * jp],     a[mt], b0, b1);
                    mma16816(acc[mt][2 * jp + 1], a[mt], b2, b3);
                }
            }
        }
    }

    // ncol(jn) = nb + (jn>>1)*32 + (jn&1)*8 + tq*2
    if (mode == 3) {
#pragma unroll
        for (int mt = 0; mt < 4; mt++) {
            int r = bm + wm * 64 + mt * 16 + g;
#pragma unroll
            for (int jn = 0; jn < 4; jn++) {
                int n = bn + nb + ((jn >> 1) << 5) + ((jn & 1) << 3) + tq * 2;
                float b0 = bias[n], b1 = bias[n + 1];
                *(float2*)(out32 + (long)r * EE + n) =
                    make_float2(acc[mt][jn][0] + b0, acc[mt][jn][1] + b1);
                *(float2*)(out32 + (long)(r + 8) * EE + n) =
                    make_float2(acc[mt][jn][2] + b0, acc[mt][jn][3] + b1);
            }
        }
        return;
    }

    if (mode == 2) {   // V -> [b,h,d,s] direct scatter (round-7 proven pattern)
        int b_ = bm >> 11;
#pragma unroll
        for (int mt = 0; mt < 4; mt++) {
            int s0 = (bm & 2047) + wm * 64 + mt * 16 + g;
#pragma unroll
            for (int jn = 0; jn < 4; jn++) {
                int dg = bn + nb + ((jn >> 1) << 5) + ((jn & 1) << 3) + tq * 2;
                int h = dg >> 6, d = dg & 63;
                float b0 = bias[dg], b1 = bias[dg + 1];
                long base = (long)(b_ * HH + h) * DD;
                g_vt[(base + d    ) * SS + s0    ] = __float2half(acc[mt][jn][0] + b0);
                g_vt[(base + d + 1) * SS + s0    ] = __float2half(acc[mt][jn][1] + b1);
                g_vt[(base + d    ) * SS + s0 + 8] = __float2half(acc[mt][jn][2] + b0);
                g_vt[(base + d + 1) * SS + s0 + 8] = __float2half(acc[mt][jn][3] + b1);
            }
        }
        return;
    }

    // RoPE (modes 0/1): acc[mt][jn] (x1) pairs with acc[mt][jn+2] (x2), jn in {0,1}
    __half* qk = (mode == 0) ? g_q : g_k;
    int b_ = bm >> 11;
    int h = (bn >> 6) + (wn >> 1);
    long rowbase = (long)(b_ * HH + h) * SS;
#pragma unroll
    for (int jn = 0; jn < 2; jn++) {
        int c1 = (wn & 1) * 16 + jn * 8 + tq * 2;   // within-head x1 col (0..30 even)
        float be0 = bias[h * 64 + c1],      be1 = bias[h * 64 + c1 + 1];
        float bo0 = bias[h * 64 + 32 + c1], bo1 = bias[h * 64 + 32 + c1 + 1];
#pragma unroll
        for (int mt = 0; mt < 4; mt++) {
            int srow = (bm & 2047) + wm * 64 + mt * 16 + g;
#pragma unroll
            for (int rr = 0; rr < 2; rr++) {
                int s = srow + rr * 8;
                float2 cs0 = g_rope[s * 32 + c1];
                float2 cs1 = g_rope[s * 32 + c1 + 1];
                float x1a = acc[mt][jn][rr * 2]     + be0;
                float x1b = acc[mt][jn][rr * 2 + 1] + be1;
                float x2a = acc[mt][jn + 2][rr * 2]     + bo0;
                float x2b = acc[mt][jn + 2][rr * 2 + 1] + bo1;
                __half2 lo = __floats2half2_rn(x1a * cs0.x - x2a * cs0.y,
                                               x1b * cs1.x - x2b * cs1.y);
                __half2 hi = __floats2half2_rn(x2a * cs0.x + x1a * cs0.y,
                                               x2b * cs1.x + x1b * cs1.y);
                *(__half2*)(qk + (rowbase + s) * DD + c1)      = lo;
                *(__half2*)(qk + (rowbase + s) * DD + c1 + 32) = hi;
            }
        }
    }
}

// ---------------- flash attention (proven round-7 version, verbatim) --------
__global__ __launch_bounds__(256) void flash_kernel() {
    int bh = blockIdx.y;
    int b_ = bh >> 4;
    int h  = bh & 15;
    int qt = blockIdx.x;

    __shared__ __align__(16) __half Qs[128][64];
    __shared__ __align__(16) __half Ks[2][64][64];
    __shared__ __align__(16) __half Vs[2][64][64];

    int tid = threadIdx.x, w = tid >> 5, l = tid & 31, g = l >> 2, tq = l & 3;

    const __half* Qg  = g_q  + ((long)bh * SS + qt * 128) * DD;
    const __half* Kg0 = g_k  + (long)bh * SS * DD;
    const __half* Vg0 = g_vt + (long)bh * DD * SS;

#pragma unroll
    for (int it = 0; it < 4; it++) {
        int c = tid + 256 * it, r = c >> 3, cc = c & 7;
        cp16(&Qs[r][((cc ^ (r & 7)) << 3)], Qg + r * 64 + cc * 8);
    }
    cp_commit();

#define KV_LOAD(s, t)                                                             \
    do {                                                                          \
        const __half* Kg = Kg0 + (long)(t) * 64 * DD;                             \
        const __half* Vg = Vg0 + (t) * 64;                                        \
        _Pragma("unroll")                                                         \
        for (int it = 0; it < 2; it++) {                                          \
            int c = tid + 256 * it, r = c >> 3, cc = c & 7;                       \
            cp16(&Ks[s][r][((cc ^ (r & 7)) << 3)], Kg + r * 64 + cc * 8);         \
            cp16(&Vs[s][r][((cc ^ (r & 7)) << 3)], Vg + (long)r * SS + cc * 8);   \
        }                                                                         \
    } while (0)

    KV_LOAD(0, 0);
    cp_commit();

    uint32_t QsB = (uint32_t)__cvta_generic_to_shared(&Qs[0][0]);
    uint32_t KsB = (uint32_t)__cvta_generic_to_shared(&Ks[0][0][0]);
    uint32_t VsB = (uint32_t)__cvta_generic_to_shared(&Vs[0][0][0]);
    int bi = l >> 3, rin = l & 7;

    cp_wait<1>();
    __syncthreads();

    uint32_t qf[4][4];
    {
        uint32_t qrowb = QsB + (uint32_t)((w * 16 + ((bi & 1) << 3) + rin) * 128);
        int qcb = bi >> 1;
#pragma unroll
        for (int kk = 0; kk < 4; kk++)
            ldsm4(qf[kk][0], qf[kk][1], qf[kk][2], qf[kk][3],
                  qrowb + (uint32_t)((((kk * 2 + qcb) ^ rin) << 4)));
    }

    uint32_t kvro = (uint32_t)(((((bi >> 1) << 3) + rin)) * 128);
    int kcb = bi & 1;

    float accO[8][4];
#pragma unroll
    for (int j = 0; j < 8; j++)
#pragma unroll
        for (int i = 0; i < 4; i++) accO[j][i] = 0.f;
    float mi0 = -1e30f, mi1 = -1e30f, li0 = 0.f, li1 = 0.f;

    const float* mrow = g_maskf + b_ * SS;
    const float SCALE2 = 0.18033688011112536f;   // 1/8 * log2(e)
    const uint32_t ONES = 0x3C003C00u;           // half2(1,1)

    for (int t = 0; t < SS / 64; t++) {
        cp_wait<0>();
        __syncthreads();
        if (t < SS / 64 - 1) { KV_LOAD((t + 1) & 1, t + 1); cp_commit(); }
        int s = t & 1;
        uint32_t kbase = KsB + s * 8192 + kvro;
        uint32_t vbase = VsB + s * 8192 + kvro;

        float sc[8][4];
#pragma unroll
        for (int j = 0; j < 8; j++)
#pragma unroll
            for (int i = 0; i < 4; i++) sc[j][i] = 0.f;
#pragma unroll
        for (int kk = 0; kk < 4; kk++) {
#pragma unroll
            for (int jp = 0; jp < 4; jp++) {
                uint32_t b0, b1, b2, b3;
                ldsm4(b0, b1, b2, b3, kbase + jp * 2048 + ((((kk * 2 + kcb) ^ rin)) << 4));
                mma16816(sc[2 * jp],     qf[kk], b0, b1);
                mma16816(sc[2 * jp + 1], qf[kk], b2, b3);
            }
        }
#pragma unroll
        for (int j = 0; j < 8; j++) {
            float2 mv = *(const float2*)(mrow + t * 64 + j * 8 + tq * 2);
            sc[j][0] = sc[j][0] * SCALE2 + mv.x;
            sc[j][1] = sc[j][1] * SCALE2 + mv.y;
            sc[j][2] = sc[j][2] * SCALE2 + mv.x;
            sc[j][3] = sc[j][3] * SCALE2 + mv.y;
        }
        float mx0 = -1e30f, mx1 = -1e30f;
#pragma unroll
        for (int j = 0; j < 8; j++) {
            mx0 = fmaxf(mx0, fmaxf(sc[j][0], sc[j][1]));
            mx1 = fmaxf(mx1, fmaxf(sc[j][2], sc[j][3]));
        }
        mx0 = fmaxf(mx0, __shfl_xor_sync(0xffffffff, mx0, 1));
        mx0 = fmaxf(mx0, __shfl_xor_sync(0xffffffff, mx0, 2));
        mx1 = fmaxf(mx1, __shfl_xor_sync(0xffffffff, mx1, 1));
        mx1 = fmaxf(mx1, __shfl_xor_sync(0xffffffff, mx1, 2));
        float mn0 = fmaxf(mi0, mx0), mn1 = fmaxf(mi1, mx1);
        float rs0f = exp2f(mi0 - mn0), rs1f = exp2f(mi1 - mn1);
        mi0 = mn0; mi1 = mn1;

        uint32_t pa[4][4];
#pragma unroll
        for (int j = 0; j < 8; j++) {
            __half2 h01 = __floats2half2_rn(sc[j][0] - mn0, sc[j][1] - mn0);
            __half2 h23 = __floats2half2_rn(sc[j][2] - mn1, sc[j][3] - mn1);
            uint32_t p01 = h2exp2(*(uint32_t*)&h01);
            uint32_t p23 = h2exp2(*(uint32_t*)&h23);
            int kk = j >> 1;
            if ((j & 1) == 0) { pa[kk][0] = p01; pa[kk][1] = p23; }
            else             { pa[kk][2] = p01; pa[kk][3] = p23; }
        }
        float accS[4] = {0.f, 0.f, 0.f, 0.f};
#pragma unroll
        for (int kk = 0; kk < 4; kk++)
            mma16816(accS, pa[kk], ONES, ONES);
        li0 = li0 * rs0f + accS[0];
        li1 = li1 * rs1f + accS[2];
#pragma unroll
        for (int j = 0; j < 8; j++) {
            accO[j][0] *= rs0f; accO[j][1] *= rs0f;
            accO[j][2] *= rs1f; accO[j][3] *= rs1f;
        }
#pragma unroll
        for (int kk = 0; kk < 4; kk++) {
#pragma unroll
            for (int jp = 0; jp < 4; jp++) {
                uint32_t b0, b1, b2, b3;
                ldsm4(b0, b1, b2, b3, vbase + jp * 2048 + ((((kk * 2 + kcb) ^ rin)) << 4));
                mma16816(accO[2 * jp],     pa[kk], b0, b1);
                mma16816(accO[2 * jp + 1], pa[kk], b2, b3);
            }
        }
    }

    float inv0 = 1.f / li0, inv1 = 1.f / li1;
    int q0 = qt * 128 + w * 16 + g;
    long row0 = (long)(b_ * SS + q0) * EE + h * 64;
    long row1 = (long)(b_ * SS + q0 + 8) * EE + h * 64;
#pragma unroll
    for (int j = 0; j < 8; j++) {
        int d0 = j * 8 + tq * 2;
        __half2 o0 = __floats2half2_rn(accO[j][0] * inv0, accO[j][1] * inv0);
        __half2 o1 = __floats2half2_rn(accO[j][2] * inv1, accO[j][3] * inv1);
        *(__half2*)(g_oc + row0 + d0) = o0;
        *(__half2*)(g_oc + row1 + d0) = o1;
    }
}

// ---------------- launch ----------------
extern "C" void kernel_launch(void* const* d_in, const int* in_sizes, int n_in,
                              void* d_out, int out_size) {
    const float* x  = (const float*)d_in[0];
    const float* Wq = (const float*)d_in[1];
    const float* bq = (const float*)d_in[2];
    const float* Wk = (const float*)d_in[3];
    const float* bk = (const float*)d_in[4];
    const float* Wv = (const float*)d_in[5];
    const float* bv = (const float*)d_in[6];
    const float* Wo = (const float*)d_in[7];
    const float* bo = (const float*)d_in[8];
    const unsigned char* mask = (const unsigned char*)d_in[9];
    float* out = (float*)d_out;

    cvt_x_misc_kernel<<<MM * EE / 1024 + 256, 256>>>(x, mask);           // 0
    cvt_w_kernel<<<dim3(32, 32, 4), dim3(32, 8)>>>(Wq, Wk, Wv, Wo);      // 1
    gemm_kernel<<<dim3(8, 64, 3), 256>>>(0, bq, bk, bv, nullptr);        // 2 (QKV)
    flash_kernel<<<dim3(SS / 128, BB * HH), 256>>>();                    // 3 (ncu target)
    gemm_kernel<<<dim3(8, 64, 1), 256>>>(1, bo, bo, bo, out);            // 4
}

// round 10
// speedup vs baseline: 2.0423x; 1.0458x over previous
#include <cuda_runtime.h>
#include <cuda_fp16.h>
#include <cstdint>

#define BB 4
#define SS 2048
#define EE 1024
#define HH 16
#define DD 64
#define MM (BB*SS)   // 8192 tokens

// ---------------- static scratch ----------------
__device__ __align__(256) __half g_xh[MM*EE];
__device__ __align__(256) __half g_wt[4][EE*EE];      // transposed [n][k]
__device__ __align__(256) __half g_q [BB*HH*SS*DD];   // [b,h,s,d]  (pre-scaled by 1/8*log2e)
__device__ __align__(256) __half g_k [BB*HH*SS*DD];   // [b,h,s,d]
__device__ __align__(256) __half g_vt[BB*HH*DD*SS];   // [b,h,d,s]
__device__ __align__(256) __half g_oc[MM*EE];         // [tok, h*64+d]
__device__ __half g_maskh[BB*SS];                     // 0 or -inf (fp16)
__device__ float2 g_rope[SS*32];                      // (cos,sin) per (s, pair idx)

// ---------------- PTX helpers ----------------
__device__ __forceinline__ void mma16816(float c[4], const uint32_t a[4],
                                         uint32_t b0, uint32_t b1) {
    asm volatile(
        "mma.sync.aligned.m16n8k16.row.col.f32.f16.f16.f32 "
        "{%0,%1,%2,%3}, {%4,%5,%6,%7}, {%8,%9}, {%0,%1,%2,%3};\n"
        : "+f"(c[0]), "+f"(c[1]), "+f"(c[2]), "+f"(c[3])
        : "r"(a[0]), "r"(a[1]), "r"(a[2]), "r"(a[3]), "r"(b0), "r"(b1));
}
__device__ __forceinline__ void ldsm4(uint32_t &r0, uint32_t &r1,
                                      uint32_t &r2, uint32_t &r3, uint32_t a) {
    asm volatile("ldmatrix.sync.aligned.m8n8.x4.shared.b16 {%0,%1,%2,%3}, [%4];\n"
                 : "=r"(r0), "=r"(r1), "=r"(r2), "=r"(r3) : "r"(a));
}
__device__ __forceinline__ void cp16(void* dst, const void* src) {
    uint32_t d = (uint32_t)__cvta_generic_to_shared(dst);
    asm volatile("cp.async.cg.shared.global [%0], [%1], 16;\n" :: "r"(d), "l"(src));
}
__device__ __forceinline__ void cp_commit() { asm volatile("cp.async.commit_group;\n"); }
template<int N> __device__ __forceinline__ void cp_wait() {
    asm volatile("cp.async.wait_group %0;\n" :: "n"(N));
}
__device__ __forceinline__ uint32_t h2exp2(uint32_t x) {
    uint32_t r;
    asm volatile("ex2.approx.f16x2 %0, %1;\n" : "=r"(r) : "r"(x));
    return r;
}

// ---------------- conversions ----------------
__global__ void cvt_x_misc_kernel(const float* __restrict__ x,
                                  const unsigned char* __restrict__ m) {
    if (blockIdx.x < MM * EE / 1024) {
        int i = (blockIdx.x * blockDim.x + threadIdx.x) * 4;
        float4 v = *(const float4*)(x + i);
        __half2* o = (__half2*)(g_xh + i);
        o[0] = __floats2half2_rn(v.x, v.y);
        o[1] = __floats2half2_rn(v.z, v.w);
    } else {
        int i = (blockIdx.x - MM * EE / 1024) * blockDim.x + threadIdx.x;  // SS*32
        int s = i >> 5, j = i & 31;
        const float LOG2_BASE = 13.28771237954945f;   // log2(10000)
        float invf = exp2f(-(float)j * (LOG2_BASE / 32.f));
        float sn, cs;
        sincosf((float)s * invf, &sn, &cs);
        g_rope[i] = make_float2(cs, sn);
        if (i < BB * SS) g_maskh[i] = __float2half(m[i] ? -1e30f : 0.f);  // -> -inf / 0
    }
}
// W [k][n] fp32 -> g_wt[slot] / g_wt[slot+1] (two weights per launch)
__global__ void cvt_w_kernel(const float* Wa, const float* Wb, int slot) {
    int z = slot + blockIdx.z;
    const float* W = blockIdx.z ? Wb : Wa;
    __shared__ float t[32][33];
    int bx = blockIdx.x * 32, by = blockIdx.y * 32;
#pragma unroll
    for (int i = 0; i < 32; i += 8)
        t[threadIdx.y + i][threadIdx.x] = W[(by + threadIdx.y + i) * EE + bx + threadIdx.x];
    __syncthreads();
#pragma unroll
    for (int i = 0; i < 32; i += 8)
        g_wt[z][(bx + threadIdx.y + i) * EE + (by + threadIdx.x)] =
            __float2half(t[threadIdx.x][threadIdx.y + i]);
}

// ---------------- GEMM: BM=128 BN=128 BK=32 (proven round-9 core) -----------
__global__ __launch_bounds__(256) void gemm_kernel(int final_,
                                                   const float* __restrict__ bias0,
                                                   const float* __restrict__ bias1,
                                                   const float* __restrict__ bias2,
                                                   float* __restrict__ out32) {
    int mode = final_ ? 3 : blockIdx.z;
    const float* bias = (mode == 1) ? bias1 : (mode == 2) ? bias2 : bias0;
    const __half* A  = (mode == 3) ? g_oc : g_xh;
    const __half* Bw = g_wt[mode];

    __shared__ __align__(16) __half As[2][128][40];
    __shared__ __align__(16) __half Bs[2][128][40];

    int tid = threadIdx.x, w = tid >> 5, l = tid & 31;
    int wm = w >> 2, wn = w & 3, g = l >> 2, tq = l & 3;
    int bi = l >> 3, rin = l & 7;
    int bm = blockIdx.y * 128, bn = blockIdx.x * 128;
    int nb = (wn >> 1) * 64 + (wn & 1) * 16;

    float acc[4][4][4];
#pragma unroll
    for (int mt = 0; mt < 4; mt++)
#pragma unroll
        for (int jn = 0; jn < 4; jn++)
#pragma unroll
            for (int i = 0; i < 4; i++) acc[mt][jn][i] = 0.f;

    const __half* Ap = A  + (long)bm * EE;
    const __half* Bp = Bw + (long)bn * EE;
    int lr = tid >> 2, lc = (tid & 3) * 8;

    uint32_t AsB = (uint32_t)__cvta_generic_to_shared(&As[0][0][0]);
    uint32_t BsB = (uint32_t)__cvta_generic_to_shared(&Bs[0][0][0]);
    uint32_t aoff = (uint32_t)(((wm * 64 + ((bi & 1) << 3) + rin) * 40 + ((bi >> 1) << 3)) * 2);
    uint32_t boff = (uint32_t)(((nb + ((bi >> 1) << 3) + rin) * 40 + ((bi & 1) << 3)) * 2);

#define GEMM_LOAD(s, k0)                                                          \
    do {                                                                          \
        cp16(&As[s][lr][lc],      Ap + (long)lr * EE + (k0) + lc);                \
        cp16(&As[s][lr + 64][lc], Ap + (long)(lr + 64) * EE + (k0) + lc);         \
        cp16(&Bs[s][lr][lc],      Bp + (long)lr * EE + (k0) + lc);                \
        cp16(&Bs[s][lr + 64][lc], Bp + (long)(lr + 64) * EE + (k0) + lc);         \
    } while (0)

    GEMM_LOAD(0, 0);
    cp_commit();

    for (int i = 0; i < 32; i++) {
        cp_wait<0>();
        __syncthreads();
        if (i < 31) { GEMM_LOAD((i + 1) & 1, (i + 1) * 32); cp_commit(); }
        int s = i & 1;
        uint32_t abase = AsB + s * 10240 + aoff;
        uint32_t bbase = BsB + s * 10240 + boff;
#pragma unroll
        for (int kk = 0; kk < 2; kk++) {
            uint32_t a[4][4];
#pragma unroll
            for (int mt = 0; mt < 4; mt++)
                ldsm4(a[mt][0], a[mt][1], a[mt][2], a[mt][3], abase + mt * 1280 + kk * 32);
#pragma unroll
            for (int jp = 0; jp < 2; jp++) {
                uint32_t b0, b1, b2, b3;
                ldsm4(b0, b1, b2, b3, bbase + jp * 2560 + kk * 32);
#pragma unroll
                for (int mt = 0; mt < 4; mt++) {
                    mma16816(acc[mt][2 * jp],     a[mt], b0, b1);
                    mma16816(acc[mt][2 * jp + 1], a[mt], b2, b3);
                }
            }
        }
    }

    if (mode == 3) {
#pragma unroll
        for (int mt = 0; mt < 4; mt++) {
            int r = bm + wm * 64 + mt * 16 + g;
#pragma unroll
            for (int jn = 0; jn < 4; jn++) {
                int n = bn + nb + ((jn >> 1) << 5) + ((jn & 1) << 3) + tq * 2;
                float b0 = bias[n], b1 = bias[n + 1];
                *(float2*)(out32 + (long)r * EE + n) =
                    make_float2(acc[mt][jn][0] + b0, acc[mt][jn][1] + b1);
                *(float2*)(out32 + (long)(r + 8) * EE + n) =
                    make_float2(acc[mt][jn][2] + b0, acc[mt][jn][3] + b1);
            }
        }
        return;
    }

    if (mode == 2) {   // V -> [b,h,d,s]
        int b_ = bm >> 11;
#pragma unroll
        for (int mt = 0; mt < 4; mt++) {
            int s0 = (bm & 2047) + wm * 64 + mt * 16 + g;
#pragma unroll
            for (int jn = 0; jn < 4; jn++) {
                int dg = bn + nb + ((jn >> 1) << 5) + ((jn & 1) << 3) + tq * 2;
                int h = dg >> 6, d = dg & 63;
                float b0 = bias[dg], b1 = bias[dg + 1];
                long base = (long)(b_ * HH + h) * DD;
                g_vt[(base + d    ) * SS + s0    ] = __float2half(acc[mt][jn][0] + b0);
                g_vt[(base + d + 1) * SS + s0    ] = __float2half(acc[mt][jn][1] + b1);
                g_vt[(base + d    ) * SS + s0 + 8] = __float2half(acc[mt][jn][2] + b0);
                g_vt[(base + d + 1) * SS + s0 + 8] = __float2half(acc[mt][jn][3] + b1);
            }
        }
        return;
    }

    // RoPE (modes 0/1): acc[mt][jn] (x1) pairs with acc[mt][jn+2] (x2), jn in {0,1}
    // mode 0 (Q): fold softmax scale 1/8*log2(e) into cos/sin.
    __half* qk = (mode == 0) ? g_q : g_k;
    float sf = (mode == 0) ? 0.18033688011112536f : 1.0f;
    int b_ = bm >> 11;
    int h = (bn >> 6) + (wn >> 1);
    long rowbase = (long)(b_ * HH + h) * SS;
#pragma unroll
    for (int jn = 0; jn < 2; jn++) {
        int c1 = (wn & 1) * 16 + jn * 8 + tq * 2;
        float be0 = bias[h * 64 + c1],      be1 = bias[h * 64 + c1 + 1];
        float bo0 = bias[h * 64 + 32 + c1], bo1 = bias[h * 64 + 32 + c1 + 1];
#pragma unroll
        for (int mt = 0; mt < 4; mt++) {
            int srow = (bm & 2047) + wm * 64 + mt * 16 + g;
#pragma unroll
            for (int rr = 0; rr < 2; rr++) {
                int s = srow + rr * 8;
                float2 cs0 = g_rope[s * 32 + c1];
                float2 cs1 = g_rope[s * 32 + c1 + 1];
                cs0.x *= sf; cs0.y *= sf; cs1.x *= sf; cs1.y *= sf;
                float x1a = acc[mt][jn][rr * 2]     + be0;
                float x1b = acc[mt][jn][rr * 2 + 1] + be1;
                float x2a = acc[mt][jn + 2][rr * 2]     + bo0;
                float x2b = acc[mt][jn + 2][rr * 2 + 1] + bo1;
                __half2 lo = __floats2half2_rn(x1a * cs0.x - x2a * cs0.y,
                                               x1b * cs1.x - x2b * cs1.y);
                __half2 hi = __floats2half2_rn(x2a * cs0.x + x1a * cs0.y,
                                               x2b * cs1.x + x1b * cs1.y);
                *(__half2*)(qk + (rowbase + s) * DD + c1)      = lo;
                *(__half2*)(qk + (rowbase + s) * DD + c1 + 32) = hi;
            }
        }
    }
}

// ---------------- flash attention: pre-scaled Q, smem fp16 mask -------------
__global__ __launch_bounds__(256) void flash_kernel() {
    int bh = blockIdx.y;
    int b_ = bh >> 4;
    int h  = bh & 15;
    int qt = blockIdx.x;

    __shared__ __align__(16) __half Qs[128][64];
    __shared__ __align__(16) __half Ks[2][64][64];
    __shared__ __align__(16) __half Vs[2][64][64];
    __shared__ __align__(16) __half Ms[SS];          // fp16 mask row (0 / -inf), 4KB

    int tid = threadIdx.x, w = tid >> 5, l = tid & 31, tq = l & 3;

    const __half* Qg  = g_q  + ((long)bh * SS + qt * 128) * DD;
    const __half* Kg0 = g_k  + (long)bh * SS * DD;
    const __half* Vg0 = g_vt + (long)bh * DD * SS;

#pragma unroll
    for (int it = 0; it < 4; it++) {
        int c = tid + 256 * it, r = c >> 3, cc = c & 7;
        cp16(&Qs[r][((cc ^ (r & 7)) << 3)], Qg + r * 64 + cc * 8);
    }
    cp16(&Ms[tid * 8], g_maskh + b_ * SS + tid * 8);   // 256*8 = 2048 halfs
    cp_commit();

#define KV_LOAD(s, t)                                                             \
    do {                                                                          \
        const __half* Kg = Kg0 + (long)(t) * 64 * DD;                             \
        const __half* Vg = Vg0 + (t) * 64;                                        \
        _Pragma("unroll")                                                         \
        for (int it = 0; it < 2; it++) {                                          \
            int c = tid + 256 * it, r = c >> 3, cc = c & 7;                       \
            cp16(&Ks[s][r][((cc ^ (r & 7)) << 3)], Kg + r * 64 + cc * 8);         \
            cp16(&Vs[s][r][((cc ^ (r & 7)) << 3)], Vg + (long)r * SS + cc * 8);   \
        }                                                                         \
    } while (0)

    KV_LOAD(0, 0);
    cp_commit();

    uint32_t QsB = (uint32_t)__cvta_generic_to_shared(&Qs[0][0]);
    uint32_t KsB = (uint32_t)__cvta_generic_to_shared(&Ks[0][0][0]);
    uint32_t VsB = (uint32_t)__cvta_generic_to_shared(&Vs[0][0][0]);
    int bi = l >> 3, rin = l & 7;

    cp_wait<1>();
    __syncthreads();

    uint32_t qf[4][4];
    {
        uint32_t qrowb = QsB + (uint32_t)((w * 16 + ((bi & 1) << 3) + rin) * 128);
        int qcb = bi >> 1;
#pragma unroll
        for (int kk = 0; kk < 4; kk++)
            ldsm4(qf[kk][0], qf[kk][1], qf[kk][2], qf[kk][3],
                  qrowb + (uint32_t)((((kk * 2 + qcb) ^ rin) << 4)));
    }

    uint32_t kvro = (uint32_t)(((((bi >> 1) << 3) + rin)) * 128);
    int kcb = bi & 1;

    float accO[8][4];
#pragma unroll
    for (int j = 0; j < 8; j++)
#pragma unroll
        for (int i = 0; i < 4; i++) accO[j][i] = 0.f;
    float mi0 = -1e30f, mi1 = -1e30f, li0 = 0.f, li1 = 0.f;

    const uint32_t ONES = 0x3C003C00u;           // half2(1,1)

    for (int t = 0; t < SS / 64; t++) {
        cp_wait<0>();
        __syncthreads();
        if (t < SS / 64 - 1) { KV_LOAD((t + 1) & 1, t + 1); cp_commit(); }
        int s = t & 1;
        uint32_t kbase = KsB + s * 8192 + kvro;
        uint32_t vbase = VsB + s * 8192 + kvro;

        // S = Q @ K^T  (already in log2 scale; mask applied later in fp16)
        float sc[8][4];
#pragma unroll
        for (int j = 0; j < 8; j++)
#pragma unroll
            for (int i = 0; i < 4; i++) sc[j][i] = 0.f;
#pragma unroll
        for (int kk = 0; kk < 4; kk++) {
#pragma unroll
            for (int jp = 0; jp < 4; jp++) {
                uint32_t b0, b1, b2, b3;
                ldsm4(b0, b1, b2, b3, kbase + jp * 2048 + ((((kk * 2 + kcb) ^ rin)) << 4));
                mma16816(sc[2 * jp],     qf[kk], b0, b1);
                mma16816(sc[2 * jp + 1], qf[kk], b2, b3);
            }
        }
        // row max over unmasked scores
        float mx0 = -1e30f, mx1 = -1e30f;
#pragma unroll
        for (int j = 0; j < 8; j++) {
            mx0 = fmaxf(mx0, fmaxf(sc[j][0], sc[j][1]));
            mx1 = fmaxf(mx1, fmaxf(sc[j][2], sc[j][3]));
        }
        mx0 = fmaxf(mx0, __shfl_xor_sync(0xffffffff, mx0, 1));
        mx0 = fmaxf(mx0, __shfl_xor_sync(0xffffffff, mx0, 2));
        mx1 = fmaxf(mx1, __shfl_xor_sync(0xffffffff, mx1, 1));
        mx1 = fmaxf(mx1, __shfl_xor_sync(0xffffffff, mx1, 2));
        float mn0 = fmaxf(mi0, mx0), mn1 = fmaxf(mi1, mx1);
        float rs0f = exp2f(mi0 - mn0), rs1f = exp2f(mi1 - mn1);
        mi0 = mn0; mi1 = mn1;

        // P = 2^(S - m + mask) in fp16 (mask -inf -> P = 0)
        uint32_t pa[4][4];
#pragma unroll
        for (int j = 0; j < 8; j++) {
            __half2 mvh = *(const __half2*)&Ms[t * 64 + j * 8 + tq * 2];
            __half2 h01 = __floats2half2_rn(sc[j][0] - mn0, sc[j][1] - mn0);
            __half2 h23 = __floats2half2_rn(sc[j][2] - mn1, sc[j][3] - mn1);
            h01 = __hadd2(h01, mvh);
            h23 = __hadd2(h23, mvh);
            uint32_t p01 = h2exp2(*(uint32_t*)&h01);
            uint32_t p23 = h2exp2(*(uint32_t*)&h23);
            int kk = j >> 1;
            if ((j & 1) == 0) { pa[kk][0] = p01; pa[kk][1] = p23; }
            else             { pa[kk][2] = p01; pa[kk][3] = p23; }
        }
        // row sums via tensor core (B = ones)
        float accS[4] = {0.f, 0.f, 0.f, 0.f};
#pragma unroll
        for (int kk = 0; kk < 4; kk++)
            mma16816(accS, pa[kk], ONES, ONES);
        li0 = li0 * rs0f + accS[0];
        li1 = li1 * rs1f + accS[2];
#pragma unroll
        for (int j = 0; j < 8; j++) {
            accO[j][0] *= rs0f; accO[j][1] *= rs0f;
            accO[j][2] *= rs1f; accO[j][3] *= rs1f;
        }
        // O += P @ V
#pragma unroll
        for (int kk = 0; kk < 4; kk++) {
#pragma unroll
            for (int jp = 0; jp < 4; jp++) {
                uint32_t b0, b1, b2, b3;
                ldsm4(b0, b1, b2, b3, vbase + jp * 2048 + ((((kk * 2 + kcb) ^ rin)) << 4));
                mma16816(accO[2 * jp],     pa[kk], b0, b1);
                mma16816(accO[2 * jp + 1], pa[kk], b2, b3);
            }
        }
    }

    int g = l >> 2;
    float inv0 = 1.f / li0, inv1 = 1.f / li1;
    int q0 = qt * 128 + w * 16 + g;
    long row0 = (long)(b_ * SS + q0) * EE + h * 64;
    long row1 = (long)(b_ * SS + q0 + 8) * EE + h * 64;
#pragma unroll
    for (int j = 0; j < 8; j++) {
        int d0 = j * 8 + tq * 2;
        __half2 o0 = __floats2half2_rn(accO[j][0] * inv0, accO[j][1] * inv0);
        __half2 o1 = __floats2half2_rn(accO[j][2] * inv1, accO[j][3] * inv1);
        *(__half2*)(g_oc + row0 + d0) = o0;
        *(__half2*)(g_oc + row1 + d0) = o1;
    }
}

// ---------------- launch ----------------
extern "C" void kernel_launch(void* const* d_in, const int* in_sizes, int n_in,
                              void* d_out, int out_size) {
    const float* x  = (const float*)d_in[0];
    const float* Wq = (const float*)d_in[1];
    const float* bq = (const float*)d_in[2];
    const float* Wk = (const float*)d_in[3];
    const float* bk = (const float*)d_in[4];
    const float* Wv = (const float*)d_in[5];
    const float* bv = (const float*)d_in[6];
    const float* Wo = (const float*)d_in[7];
    const float* bo = (const float*)d_in[8];
    const unsigned char* mask = (const unsigned char*)d_in[9];
    float* out = (float*)d_out;

    cvt_x_misc_kernel<<<MM * EE / 1024 + 256, 256>>>(x, mask);            // 0
    cvt_w_kernel<<<dim3(32, 32, 2), dim3(32, 8)>>>(Wq, Wk, 0);            // 1
    cvt_w_kernel<<<dim3(32, 32, 2), dim3(32, 8)>>>(Wv, Wo, 2);            // 2
    gemm_kernel<<<dim3(8, 64, 3), 256>>>(0, bq, bk, bv, nullptr);         // 3 (QKV, ncu)
    flash_kernel<<<dim3(SS / 128, BB * HH), 256>>>();                     // 4
    gemm_kernel<<<dim3(8, 64, 1), 256>>>(1, bo, bo, bo, out);             // 5
}